// round 1
// baseline (speedup 1.0000x reference)
#include <cuda_runtime.h>

// Problem constants
#define PB 2
#define PH 12
#define PT 2048
#define PD 64
#define PR 16
#define PD_STD 48
#define PBH (PB * PH)

#define QT 64
#define KT 64

// Scratch for augmented Q/K (device globals: allocation-free per harness rules)
__device__ float g_Qaug[PBH * PT * PD];
__device__ float g_Kaug[PBH * PT * PD];

// ---------------------------------------------------------------------------
// Prologue: build Q_aug / K_aug.
//   Q_aug[...,d] = sqrt(w_std[h]) * Q[...,d]            for d < 48
//   Q_aug[...,48+r] = sqrt(w_rec[h]) * (K @ W_recip)[r]   (note the cross!)
//   K_aug[...,d] = sqrt(w_std[h]) * K[...,d]            for d < 48
//   K_aug[...,48+r] = sqrt(w_rec[h]) * (Q @ W_recip)[r]
// One block = 4 rows, 64 threads per row (thread d owns output element d).
// ---------------------------------------------------------------------------
__global__ __launch_bounds__(256) void aug_kernel(
    const float* __restrict__ Q, const float* __restrict__ K,
    const float* __restrict__ W,
    const float* __restrict__ w_std, const float* __restrict__ w_rec)
{
    __shared__ float sW[PD * PR];
    __shared__ float sQ[4][PD];
    __shared__ float sK[4][PD];

    const int tid = threadIdx.x;
    for (int i = tid; i < PD * PR; i += 256) sW[i] = W[i];

    const int lr = tid >> 6;        // local row 0..3
    const int d  = tid & 63;
    const int row = blockIdx.x * 4 + lr;   // row over B*H*T
    const int h = (row / PT) % PH;

    const float q = Q[(size_t)row * PD + d];
    const float k = K[(size_t)row * PD + d];
    sQ[lr][d] = q;
    sK[lr][d] = k;
    __syncthreads();

    const float sstd = sqrtf(w_std[h]);
    const float srec = sqrtf(w_rec[h]);

    float qa, ka;
    if (d < PD_STD) {
        qa = sstd * q;
        ka = sstd * k;
    } else {
        const int r = d - PD_STD;
        float kl = 0.f, ql = 0.f;
#pragma unroll
        for (int j = 0; j < PD; j++) {
            kl = fmaf(sK[lr][j], sW[j * PR + r], kl);
            ql = fmaf(sQ[lr][j], sW[j * PR + r], ql);
        }
        qa = srec * kl;   // Q_aug tail uses K_low
        ka = srec * ql;   // K_aug tail uses Q_low
    }
    g_Qaug[(size_t)row * PD + d] = qa;
    g_Kaug[(size_t)row * PD + d] = ka;
}

// ---------------------------------------------------------------------------
// Flash attention over Q_aug/K_aug/V with causal mask + additive key bias.
// CTA = one (head, q-tile of 64). 256 threads as 16x16, 4x4 register microtile.
// Dynamic smem layout (floats):
//   sQ [64][64]   pitch 64 (reads are lane-broadcast; writes coalesced)
//   sK [64][65]   pitch 65 (kills 16-way conflict on b-operand reads)
//   sV [64][64]   pitch 64 (float4 b-reads in PV, 16B aligned)
//   sP [64][65]   pitch 65
// Total 66048 B -> 3 CTAs/SM.
// ---------------------------------------------------------------------------
__global__ __launch_bounds__(256) void attn_kernel(
    const float* __restrict__ V, const float* __restrict__ d_bias,
    const float* __restrict__ w_disc, float* __restrict__ out)
{
    extern __shared__ float smem[];
    float* sQ = smem;                      // 64*64 = 4096
    float* sK = sQ + QT * PD;              // 64*65 = 4160
    float* sV = sK + KT * 65;              // 64*64 = 4096
    float* sP = sV + KT * PD;              // 64*65 = 4160

    const int bh = blockIdx.y;
    const int q_tile = (gridDim.x - 1) - blockIdx.x;  // heavy tiles launch first
    const int h = bh % PH;
    const size_t base = (size_t)bh * PT * PD;
    const float* Qg = g_Qaug + base + (size_t)q_tile * QT * PD;
    const float* Kg = g_Kaug + base;
    const float* Vg = V + base;
    const float* bg = d_bias + (size_t)bh * PT;
    const float wd = w_disc[h];

    const int tid = threadIdx.x;
    const int tx = tid & 15;
    const int ty = tid >> 4;
    const int r0 = ty * 4;
    const int c0 = tx * 4;

    // Load Q tile (coalesced; pitch 64)
    for (int i = tid; i < QT * PD; i += 256) sQ[i] = Qg[i];

    float acc[4][4];
    float mrow[4], lrow[4];
#pragma unroll
    for (int i = 0; i < 4; i++) {
        mrow[i] = -1e30f;
        lrow[i] = 0.f;
#pragma unroll
        for (int j = 0; j < 4; j++) acc[i][j] = 0.f;
    }

    for (int kt = 0; kt <= q_tile; kt++) {
        const float* Kt = Kg + (size_t)kt * KT * PD;
        const float* Vt = Vg + (size_t)kt * KT * PD;

        __syncthreads();   // previous PV done before overwriting sK/sV/sP
        for (int i = tid; i < KT * PD; i += 256) {
            const int r = i >> 6, c = i & 63;
            sK[r * 65 + c] = Kt[i];
            sV[i] = Vt[i];
        }
        __syncthreads();

        // Per-column additive bias (rank-1, broadcast over queries)
        float bias_j[4];
#pragma unroll
        for (int j = 0; j < 4; j++) bias_j[j] = wd * __ldg(&bg[kt * KT + c0 + j]);

        // S = Q_aug @ K_aug^T (4x4 microtile)
        float s[4][4];
#pragma unroll
        for (int i = 0; i < 4; i++)
#pragma unroll
            for (int j = 0; j < 4; j++) s[i][j] = 0.f;

#pragma unroll 8
        for (int d = 0; d < PD; d++) {
            const float a0 = sQ[(r0 + 0) * PD + d];
            const float a1 = sQ[(r0 + 1) * PD + d];
            const float a2 = sQ[(r0 + 2) * PD + d];
            const float a3 = sQ[(r0 + 3) * PD + d];
            const float b0 = sK[(c0 + 0) * 65 + d];
            const float b1 = sK[(c0 + 1) * 65 + d];
            const float b2 = sK[(c0 + 2) * 65 + d];
            const float b3 = sK[(c0 + 3) * 65 + d];
            s[0][0] = fmaf(a0, b0, s[0][0]); s[0][1] = fmaf(a0, b1, s[0][1]);
            s[0][2] = fmaf(a0, b2, s[0][2]); s[0][3] = fmaf(a0, b3, s[0][3]);
            s[1][0] = fmaf(a1, b0, s[1][0]); s[1][1] = fmaf(a1, b1, s[1][1]);
            s[1][2] = fmaf(a1, b2, s[1][2]); s[1][3] = fmaf(a1, b3, s[1][3]);
            s[2][0] = fmaf(a2, b0, s[2][0]); s[2][1] = fmaf(a2, b1, s[2][1]);
            s[2][2] = fmaf(a2, b2, s[2][2]); s[2][3] = fmaf(a2, b3, s[2][3]);
            s[3][0] = fmaf(a3, b0, s[3][0]); s[3][1] = fmaf(a3, b1, s[3][1]);
            s[3][2] = fmaf(a3, b2, s[3][2]); s[3][3] = fmaf(a3, b3, s[3][3]);
        }

        // Scale, bias, causal mask
        const bool diag = (kt == q_tile);
#pragma unroll
        for (int i = 0; i < 4; i++) {
#pragma unroll
            for (int j = 0; j < 4; j++) {
                float v = fmaf(s[i][j], 0.125f, bias_j[j]);  // 1/sqrt(64)
                if (diag && (c0 + j) > (r0 + i)) v = -1e30f;
                s[i][j] = v;
            }
        }

        // Online softmax: row stats over the 16-lane column group
#pragma unroll
        for (int i = 0; i < 4; i++) {
            float rm = fmaxf(fmaxf(s[i][0], s[i][1]), fmaxf(s[i][2], s[i][3]));
#pragma unroll
            for (int off = 8; off > 0; off >>= 1)
                rm = fmaxf(rm, __shfl_xor_sync(0xffffffffu, rm, off));
            const float mnew = fmaxf(mrow[i], rm);
            const float corr = __expf(mrow[i] - mnew);
            mrow[i] = mnew;

            float rl = 0.f;
#pragma unroll
            for (int j = 0; j < 4; j++) {
                const float p = __expf(s[i][j] - mnew);
                sP[(r0 + i) * 65 + (c0 + j)] = p;
                rl += p;
            }
#pragma unroll
            for (int off = 8; off > 0; off >>= 1)
                rl += __shfl_xor_sync(0xffffffffu, rl, off);
            lrow[i] = lrow[i] * corr + rl;
#pragma unroll
            for (int j = 0; j < 4; j++) acc[i][j] *= corr;
        }
        __syncthreads();   // sP fully written before PV reads

        // O += P @ V  (float4 b-operand from sV)
#pragma unroll 8
        for (int k = 0; k < KT; k++) {
            const float a0 = sP[(r0 + 0) * 65 + k];
            const float a1 = sP[(r0 + 1) * 65 + k];
            const float a2 = sP[(r0 + 2) * 65 + k];
            const float a3 = sP[(r0 + 3) * 65 + k];
            const float4 bv = *reinterpret_cast<const float4*>(&sV[k * PD + c0]);
            acc[0][0] = fmaf(a0, bv.x, acc[0][0]); acc[0][1] = fmaf(a0, bv.y, acc[0][1]);
            acc[0][2] = fmaf(a0, bv.z, acc[0][2]); acc[0][3] = fmaf(a0, bv.w, acc[0][3]);
            acc[1][0] = fmaf(a1, bv.x, acc[1][0]); acc[1][1] = fmaf(a1, bv.y, acc[1][1]);
            acc[1][2] = fmaf(a1, bv.z, acc[1][2]); acc[1][3] = fmaf(a1, bv.w, acc[1][3]);
            acc[2][0] = fmaf(a2, bv.x, acc[2][0]); acc[2][1] = fmaf(a2, bv.y, acc[2][1]);
            acc[2][2] = fmaf(a2, bv.z, acc[2][2]); acc[2][3] = fmaf(a2, bv.w, acc[2][3]);
            acc[3][0] = fmaf(a3, bv.x, acc[3][0]); acc[3][1] = fmaf(a3, bv.y, acc[3][1]);
            acc[3][2] = fmaf(a3, bv.z, acc[3][2]); acc[3][3] = fmaf(a3, bv.w, acc[3][3]);
        }
    }

    // Normalize and write out[b,h,q,d]
    const int qrow = q_tile * QT;
#pragma unroll
    for (int i = 0; i < 4; i++) {
        const float inv = 1.0f / lrow[i];
#pragma unroll
        for (int j = 0; j < 4; j++)
            out[base + (size_t)(qrow + r0 + i) * PD + (c0 + j)] = acc[i][j] * inv;
    }
}

// ---------------------------------------------------------------------------
extern "C" void kernel_launch(void* const* d_in, const int* in_sizes, int n_in,
                              void* d_out, int out_size)
{
    const float* Q      = (const float*)d_in[0];
    const float* K      = (const float*)d_in[1];
    const float* V      = (const float*)d_in[2];
    const float* d_bias = (const float*)d_in[3];
    const float* W      = (const float*)d_in[4];
    const float* w_std  = (const float*)d_in[5];
    const float* w_rec  = (const float*)d_in[6];
    const float* w_disc = (const float*)d_in[7];
    float* out = (float*)d_out;

    const int smem_bytes = (QT * PD + KT * 65 + KT * PD + QT * 65) * 4;  // 66048
    cudaFuncSetAttribute(attn_kernel, cudaFuncAttributeMaxDynamicSharedMemorySize,
                         smem_bytes);

    aug_kernel<<<PBH * PT / 4, 256>>>(Q, K, W, w_std, w_rec);

    dim3 grid(PT / QT, PBH);
    attn_kernel<<<grid, 256, smem_bytes>>>(V, d_bias, w_disc, out);
}

// round 2
// speedup vs baseline: 2.9655x; 2.9655x over previous
#include <cuda_runtime.h>
#include <cstdint>

#define PB 2
#define PH 12
#define PT 2048
#define PD 64
#define PR 16
#define PD_STD 48
#define PBH (PB * PH)
#define QT 64
#define KT 64
#define KP 68          // smem pitch (words) for K and P tiles

// smem word offsets
#define SK0 0
#define SK1 4352
#define SV0 8704
#define SV1 12800
#define SP  16896
#define SB0 21248
#define SB1 21312
#define SMEM_WORDS 21376   // 85504 bytes

__device__ float g_Qaug[PBH * PT * PD];
__device__ float g_Kaug[PBH * PT * PD];

__device__ __forceinline__ float tf32r(float x) {
    unsigned u;
    asm("cvt.rna.tf32.f32 %0, %1;" : "=r"(u) : "f"(x));
    return __uint_as_float(u);
}

__device__ __forceinline__ void mma8(float& d0, float& d1, float& d2, float& d3,
                                     unsigned a0, unsigned a1, unsigned a2, unsigned a3,
                                     unsigned b0, unsigned b1) {
    asm volatile(
        "mma.sync.aligned.m16n8k8.row.col.f32.tf32.tf32.f32 "
        "{%0,%1,%2,%3},{%4,%5,%6,%7},{%8,%9},{%0,%1,%2,%3};"
        : "+f"(d0), "+f"(d1), "+f"(d2), "+f"(d3)
        : "r"(a0), "r"(a1), "r"(a2), "r"(a3), "r"(b0), "r"(b1));
}

__device__ __forceinline__ void cpa16(unsigned dst, const float* src) {
    asm volatile("cp.async.cg.shared.global [%0], [%1], 16;" :: "r"(dst), "l"(src));
}

// ---------------------------------------------------------------------------
// Prologue: Q_aug (scaled by 1/8, tf32-rounded), K_aug (tf32-rounded).
// ---------------------------------------------------------------------------
__global__ __launch_bounds__(256) void aug_kernel(
    const float* __restrict__ Q, const float* __restrict__ K,
    const float* __restrict__ W,
    const float* __restrict__ w_std, const float* __restrict__ w_rec)
{
    __shared__ float sW[PD * PR];
    __shared__ float sQ[4][PD];
    __shared__ float sK[4][PD];

    const int tid = threadIdx.x;
    for (int i = tid; i < PD * PR; i += 256) sW[i] = W[i];

    const int lr = tid >> 6;
    const int d  = tid & 63;
    const int row = blockIdx.x * 4 + lr;
    const int h = (row / PT) % PH;

    const float q = Q[(size_t)row * PD + d];
    const float k = K[(size_t)row * PD + d];
    sQ[lr][d] = q;
    sK[lr][d] = k;
    __syncthreads();

    const float sstd = sqrtf(w_std[h]);
    const float srec = sqrtf(w_rec[h]);

    float qa, ka;
    if (d < PD_STD) {
        qa = 0.125f * sstd * q;
        ka = sstd * k;
    } else {
        const int r = d - PD_STD;
        float kl = 0.f, ql = 0.f;
#pragma unroll
        for (int j = 0; j < PD; j++) {
            kl = fmaf(sK[lr][j], sW[j * PR + r], kl);
            ql = fmaf(sQ[lr][j], sW[j * PR + r], ql);
        }
        qa = 0.125f * srec * kl;
        ka = srec * ql;
    }
    g_Qaug[(size_t)row * PD + d] = tf32r(qa);
    g_Kaug[(size_t)row * PD + d] = tf32r(ka);
}

// ---------------------------------------------------------------------------
// Double-buffered tile loader: K (pitch 68), V (XOR-8 swizzle), bias.
// ---------------------------------------------------------------------------
__device__ __forceinline__ void load_stage(float* sm, int stage,
                                           const float* Kt, const float* Vt,
                                           const float* bt, int tid)
{
    const unsigned sbase = (unsigned)__cvta_generic_to_shared(sm);
    const unsigned kbase = sbase + (stage ? SK1 : SK0) * 4u;
    const unsigned vbase = sbase + (stage ? SV1 : SV0) * 4u;
    const unsigned bbase = sbase + (stage ? SB1 : SB0) * 4u;
#pragma unroll
    for (int i = 0; i < 8; i++) {
        const int ch = tid + i * 128;
        const int r = ch >> 4, c4 = (ch & 15) << 2;
        cpa16(kbase + (unsigned)(r * KP + c4) * 4u, Kt + r * 64 + c4);
    }
#pragma unroll
    for (int i = 0; i < 8; i++) {
        const int ch = tid + i * 128;
        const int r = ch >> 4, c4 = (ch & 15) << 2;
        const int cs = c4 ^ ((r & 7) << 3);
        cpa16(vbase + (unsigned)(r * 64 + cs) * 4u, Vt + r * 64 + c4);
    }
    if (tid < 16) cpa16(bbase + (unsigned)(tid * 4) * 4u, bt + tid * 4);
    asm volatile("cp.async.commit_group;");
}

// ---------------------------------------------------------------------------
// Flash attention, tf32 tensor-core path.
// CTA = (head, 64-row q-tile), 128 threads (4 warps, 16 rows each).
// ---------------------------------------------------------------------------
__global__ __launch_bounds__(128) void attn_kernel(
    const float* __restrict__ V, const float* __restrict__ d_bias,
    const float* __restrict__ w_disc, float* __restrict__ out)
{
    extern __shared__ float sm[];
    const int bh = blockIdx.y;
    const int q_tile = (PT / QT - 1) - blockIdx.x;   // heavy tiles first
    const int h = bh % PH;
    const size_t base = (size_t)bh * PT * PD;
    const float* Kg = g_Kaug + base;
    const float* Vg = V + base;
    const float* bg = d_bias + (size_t)bh * PT;
    const float wd = w_disc[h];

    const int tid = threadIdx.x;
    const int w = tid >> 5, lane = tid & 31;
    const int g = lane >> 2, c = lane & 3;

    // Q fragments: whole 16x64 warp tile in registers, kept for the kernel.
    unsigned qf[8][4];
    {
        const float* Qg = g_Qaug + base + ((size_t)q_tile * QT + 16 * w) * PD;
#pragma unroll
        for (int kk = 0; kk < 8; kk++) {
            qf[kk][0] = __float_as_uint(Qg[g * 64 + 8 * kk + c]);
            qf[kk][1] = __float_as_uint(Qg[(g + 8) * 64 + 8 * kk + c]);
            qf[kk][2] = __float_as_uint(Qg[g * 64 + 8 * kk + c + 4]);
            qf[kk][3] = __float_as_uint(Qg[(g + 8) * 64 + 8 * kk + c + 4]);
        }
    }

    float acc[8][4];
#pragma unroll
    for (int nb = 0; nb < 8; nb++)
#pragma unroll
        for (int j = 0; j < 4; j++) acc[nb][j] = 0.f;
    float m0 = -1e30f, m1 = -1e30f, l0 = 0.f, l1 = 0.f;

    load_stage(sm, 0, Kg, Vg, bg, tid);
    int stage = 0;

    for (int kt = 0; kt <= q_tile; kt++) {
        asm volatile("cp.async.wait_group 0;");
        __syncthreads();
        if (kt < q_tile)
            load_stage(sm, stage ^ 1, Kg + (size_t)(kt + 1) * KT * PD,
                       Vg + (size_t)(kt + 1) * KT * PD, bg + (kt + 1) * KT, tid);

        const float* sK = sm + (stage ? SK1 : SK0);
        const float* sV = sm + (stage ? SV1 : SV0);
        const float* sB = sm + (stage ? SB1 : SB0);
        float* sP = sm + SP;

        // ---- S = Q_aug @ K_aug^T (scale pre-folded), C-init = bias ----
        float s[8][4];
#pragma unroll
        for (int nb = 0; nb < 8; nb++) {
            const float2 bb = *reinterpret_cast<const float2*>(sB + 8 * nb + 2 * c);
            s[nb][0] = wd * bb.x; s[nb][1] = wd * bb.y;
            s[nb][2] = s[nb][0];  s[nb][3] = s[nb][1];
            const float* kb = sK + (8 * nb + g) * KP + c;
#pragma unroll
            for (int kk = 0; kk < 8; kk++) {
                const unsigned b0 = __float_as_uint(kb[8 * kk]);
                const unsigned b1 = __float_as_uint(kb[8 * kk + 4]);
                mma8(s[nb][0], s[nb][1], s[nb][2], s[nb][3],
                     qf[kk][0], qf[kk][1], qf[kk][2], qf[kk][3], b0, b1);
            }
        }

        if (kt == q_tile) {   // causal mask on the diagonal tile
            const int r0 = 16 * w + g, r1 = r0 + 8;
#pragma unroll
            for (int nb = 0; nb < 8; nb++) {
                const int k0 = 8 * nb + 2 * c, k1 = k0 + 1;
                if (k0 > r0) s[nb][0] = -1e30f;
                if (k1 > r0) s[nb][1] = -1e30f;
                if (k0 > r1) s[nb][2] = -1e30f;
                if (k1 > r1) s[nb][3] = -1e30f;
            }
        }

        // ---- online softmax (rows g and g+8 within warp tile) ----
        float rm0 = fmaxf(s[0][0], s[0][1]), rm1 = fmaxf(s[0][2], s[0][3]);
#pragma unroll
        for (int nb = 1; nb < 8; nb++) {
            rm0 = fmaxf(rm0, fmaxf(s[nb][0], s[nb][1]));
            rm1 = fmaxf(rm1, fmaxf(s[nb][2], s[nb][3]));
        }
        rm0 = fmaxf(rm0, __shfl_xor_sync(0xffffffffu, rm0, 1));
        rm0 = fmaxf(rm0, __shfl_xor_sync(0xffffffffu, rm0, 2));
        rm1 = fmaxf(rm1, __shfl_xor_sync(0xffffffffu, rm1, 1));
        rm1 = fmaxf(rm1, __shfl_xor_sync(0xffffffffu, rm1, 2));
        const float mn0 = fmaxf(m0, rm0), mn1 = fmaxf(m1, rm1);
        const float co0 = __expf(m0 - mn0), co1 = __expf(m1 - mn1);
        m0 = mn0; m1 = mn1;

        float rl0 = 0.f, rl1 = 0.f;
        float* pw = sP + (16 * w + g) * KP + 2 * c;
        __syncwarp();
#pragma unroll
        for (int nb = 0; nb < 8; nb++) {
            const float p00 = tf32r(__expf(s[nb][0] - mn0));
            const float p01 = tf32r(__expf(s[nb][1] - mn0));
            const float p10 = tf32r(__expf(s[nb][2] - mn1));
            const float p11 = tf32r(__expf(s[nb][3] - mn1));
            rl0 += p00 + p01; rl1 += p10 + p11;
            *reinterpret_cast<float2*>(pw + 8 * nb) = make_float2(p00, p01);
            *reinterpret_cast<float2*>(pw + 8 * KP + 8 * nb) = make_float2(p10, p11);
        }
        rl0 += __shfl_xor_sync(0xffffffffu, rl0, 1);
        rl0 += __shfl_xor_sync(0xffffffffu, rl0, 2);
        rl1 += __shfl_xor_sync(0xffffffffu, rl1, 1);
        rl1 += __shfl_xor_sync(0xffffffffu, rl1, 2);
        l0 = l0 * co0 + rl0;
        l1 = l1 * co1 + rl1;
#pragma unroll
        for (int nb = 0; nb < 8; nb++) {
            acc[nb][0] *= co0; acc[nb][1] *= co0;
            acc[nb][2] *= co1; acc[nb][3] *= co1;
        }
        __syncwarp();

        // ---- O += P @ V ----
        const float* pa0 = sP + (16 * w + g) * KP + c;
        const float* pa1 = pa0 + 8 * KP;
#pragma unroll
        for (int kk = 0; kk < 8; kk++) {
            const unsigned a0 = __float_as_uint(pa0[8 * kk]);
            const unsigned a1 = __float_as_uint(pa1[8 * kk]);
            const unsigned a2 = __float_as_uint(pa0[8 * kk + 4]);
            const unsigned a3 = __float_as_uint(pa1[8 * kk + 4]);
            const float* vrow = sV + (8 * kk + c) * 64 + g;   // XOR-8 swizzled cols
#pragma unroll
            for (int nb = 0; nb < 8; nb++) {
                const unsigned b0 = __float_as_uint(vrow[8 * (nb ^ c)]);
                const unsigned b1 = __float_as_uint(vrow[4 * 64 + 8 * (nb ^ c ^ 4)]);
                mma8(acc[nb][0], acc[nb][1], acc[nb][2], acc[nb][3],
                     a0, a1, a2, a3, b0, b1);
            }
        }
        stage ^= 1;
    }

    // ---- normalize + write ----
    const float inv0 = 1.0f / l0, inv1 = 1.0f / l1;
    float* og = out + base + ((size_t)q_tile * QT + 16 * w) * PD;
#pragma unroll
    for (int nb = 0; nb < 8; nb++) {
        *reinterpret_cast<float2*>(og + g * 64 + 8 * nb + 2 * c) =
            make_float2(acc[nb][0] * inv0, acc[nb][1] * inv0);
        *reinterpret_cast<float2*>(og + (g + 8) * 64 + 8 * nb + 2 * c) =
            make_float2(acc[nb][2] * inv1, acc[nb][3] * inv1);
    }
}

// ---------------------------------------------------------------------------
extern "C" void kernel_launch(void* const* d_in, const int* in_sizes, int n_in,
                              void* d_out, int out_size)
{
    const float* Q      = (const float*)d_in[0];
    const float* K      = (const float*)d_in[1];
    const float* V      = (const float*)d_in[2];
    const float* d_bias = (const float*)d_in[3];
    const float* W      = (const float*)d_in[4];
    const float* w_std  = (const float*)d_in[5];
    const float* w_rec  = (const float*)d_in[6];
    const float* w_disc = (const float*)d_in[7];
    float* out = (float*)d_out;

    const int smem_bytes = SMEM_WORDS * 4;   // 85504
    cudaFuncSetAttribute(attn_kernel, cudaFuncAttributeMaxDynamicSharedMemorySize,
                         smem_bytes);

    aug_kernel<<<PBH * PT / 4, 256>>>(Q, K, W, w_std, w_rec);

    dim3 grid(PT / QT, PBH);
    attn_kernel<<<grid, 128, smem_bytes>>>(V, d_bias, w_disc, out);
}

// round 3
// speedup vs baseline: 5.2929x; 1.7848x over previous
#include <cuda_runtime.h>
#include <cuda_fp16.h>
#include <cstdint>

#define PB 2
#define PH 12
#define PT 2048
#define PD 64
#define PR 16
#define PD_STD 48
#define PBH (PB * PH)
#define QT 64
#define KT 64
#define LOG2E 1.4426950408889634f

// smem byte offsets
#define SK0 0
#define SK1 8192
#define SV0 16384
#define SV1 24576
#define SPQ 32768
#define SB0 40960
#define SB1 41216
#define SMEM_BYTES 41472

__device__ __half g_Qh[PBH * PT * PD];
__device__ __half g_Kh[PBH * PT * PD];
__device__ __half g_Vh[PBH * PT * PD];
__device__ float  g_bw[PBH * PT];

__device__ __forceinline__ void mma16816(float& d0, float& d1, float& d2, float& d3,
                                         unsigned a0, unsigned a1, unsigned a2, unsigned a3,
                                         unsigned b0, unsigned b1) {
    asm volatile(
        "mma.sync.aligned.m16n8k16.row.col.f32.f16.f16.f32 "
        "{%0,%1,%2,%3},{%4,%5,%6,%7},{%8,%9},{%0,%1,%2,%3};"
        : "+f"(d0), "+f"(d1), "+f"(d2), "+f"(d3)
        : "r"(a0), "r"(a1), "r"(a2), "r"(a3), "r"(b0), "r"(b1));
}

__device__ __forceinline__ void ldsm4(unsigned& r0, unsigned& r1, unsigned& r2, unsigned& r3,
                                      unsigned addr) {
    asm volatile("ldmatrix.sync.aligned.m8n8.x4.shared.b16 {%0,%1,%2,%3}, [%4];"
                 : "=r"(r0), "=r"(r1), "=r"(r2), "=r"(r3) : "r"(addr));
}
__device__ __forceinline__ void ldsm4t(unsigned& r0, unsigned& r1, unsigned& r2, unsigned& r3,
                                       unsigned addr) {
    asm volatile("ldmatrix.sync.aligned.m8n8.x4.trans.shared.b16 {%0,%1,%2,%3}, [%4];"
                 : "=r"(r0), "=r"(r1), "=r"(r2), "=r"(r3) : "r"(addr));
}
__device__ __forceinline__ void cpa16(unsigned dst, const void* src) {
    asm volatile("cp.async.cg.shared.global [%0], [%1], 16;" :: "r"(dst), "l"(src));
}

// ---------------------------------------------------------------------------
// Prologue: fp16 Q_aug (scale 0.125*log2e folded), fp16 K_aug, fp16 V,
// pre-weighted bias (w_disc*log2e folded). One block = 4 rows over B*H*T.
// ---------------------------------------------------------------------------
__global__ __launch_bounds__(256) void aug_kernel(
    const float* __restrict__ Q, const float* __restrict__ K,
    const float* __restrict__ V, const float* __restrict__ d_bias,
    const float* __restrict__ W,
    const float* __restrict__ w_std, const float* __restrict__ w_rec,
    const float* __restrict__ w_disc)
{
    __shared__ float sW[PD * PR];
    __shared__ float sQ[4][PD];
    __shared__ float sK[4][PD];

    const int tid = threadIdx.x;
    for (int i = tid; i < PD * PR; i += 256) sW[i] = W[i];

    const int lr = tid >> 6;
    const int d  = tid & 63;
    const int row = blockIdx.x * 4 + lr;
    const int h = (row / PT) % PH;

    const float q = Q[(size_t)row * PD + d];
    const float k = K[(size_t)row * PD + d];
    sQ[lr][d] = q;
    sK[lr][d] = k;
    __syncthreads();

    const float sstd = sqrtf(w_std[h]);
    const float srec = sqrtf(w_rec[h]);
    const float SCL = 0.125f * LOG2E;

    float qa, ka;
    if (d < PD_STD) {
        qa = SCL * sstd * q;
        ka = sstd * k;
    } else {
        const int r = d - PD_STD;
        float kl = 0.f, ql = 0.f;
#pragma unroll
        for (int j = 0; j < PD; j++) {
            kl = fmaf(sK[lr][j], sW[j * PR + r], kl);
            ql = fmaf(sQ[lr][j], sW[j * PR + r], ql);
        }
        qa = SCL * srec * kl;   // Q_aug tail uses K_low
        ka = srec * ql;         // K_aug tail uses Q_low
    }
    g_Qh[(size_t)row * PD + d] = __float2half_rn(qa);
    g_Kh[(size_t)row * PD + d] = __float2half_rn(ka);
    g_Vh[(size_t)row * PD + d] = __float2half_rn(V[(size_t)row * PD + d]);
    if (d == 0) g_bw[row] = LOG2E * w_disc[h] * d_bias[row];
}

// ---------------------------------------------------------------------------
// Swizzled fp16 tile loader (64 rows x 128B, SW128 xor swizzle) + f32 bias.
// ---------------------------------------------------------------------------
__device__ __forceinline__ void load_stage(unsigned sb, int stage,
                                           const __half* Kt, const __half* Vt,
                                           const float* bt, int tid)
{
    const unsigned kb = sb + (stage ? SK1 : SK0);
    const unsigned vb = sb + (stage ? SV1 : SV0);
    const unsigned bb = sb + (stage ? SB1 : SB0);
#pragma unroll
    for (int i = 0; i < 4; i++) {
        const int ch = tid + i * 128;
        const int r = ch >> 3, a = ch & 7;
        const unsigned off = (unsigned)(r * 128 + ((a ^ (r & 7)) << 4));
        cpa16(kb + off, Kt + r * 64 + a * 8);
        cpa16(vb + off, Vt + r * 64 + a * 8);
    }
    if (tid < 16) cpa16(bb + (unsigned)tid * 16u, bt + tid * 4);
    asm volatile("cp.async.commit_group;");
}

__device__ __forceinline__ void load_qtile(unsigned sb, const __half* Qt, int tid)
{
    const unsigned qb = sb + SPQ;
#pragma unroll
    for (int i = 0; i < 4; i++) {
        const int ch = tid + i * 128;
        const int r = ch >> 3, a = ch & 7;
        cpa16(qb + (unsigned)(r * 128 + ((a ^ (r & 7)) << 4)), Qt + r * 64 + a * 8);
    }
    asm volatile("cp.async.commit_group;");
}

// ---------------------------------------------------------------------------
// Flash attention, fp16 HMMA.16816 + ldmatrix. CTA = (head, 64-row q-tile),
// 128 threads. 41.5 KB smem -> 4 CTA/SM.
// ---------------------------------------------------------------------------
__global__ __launch_bounds__(128, 4) void attn_kernel(float* __restrict__ out)
{
    extern __shared__ char sm[];
    const unsigned sb = (unsigned)__cvta_generic_to_shared(sm);

    const int bh = blockIdx.y;
    const int q_tile = (PT / QT - 1) - blockIdx.x;   // heavy tiles first
    const size_t base = (size_t)bh * PT * PD;
    const __half* Kg = g_Kh + base;
    const __half* Vg = g_Vh + base;
    const float*  bg = g_bw + (size_t)bh * PT;

    const int tid = threadIdx.x;
    const int w = tid >> 5, lane = tid & 31;
    const int g = lane >> 2, c = lane & 3;

    // per-lane ldmatrix address components
    const int kr   = 8 * (lane >> 4) + (lane & 7);        // K rows (B frags)
    const int kao  = (lane >> 3) & 1;                     // K atom offset
    const int qr   = 16 * w + 8 * ((lane >> 3) & 1) + (lane & 7);  // Q/P rows (A frags)
    const int qao  = lane >> 4;                           // Q/P atom offset
    const int vro  = 8 * ((lane >> 3) & 1) + (lane & 7);  // V row offset (trans B)
    const int vao  = lane >> 4;                           // V atom offset

    const unsigned qrow_b = sb + SPQ + (unsigned)qr * 128u;
    const int qsw = qr & 7, ksw = kr & 7, vsw = vro & 7;

    // preload Q tile into the P region, then lift fragments to registers
    load_stage(sb, 0, Kg, Vg, bg, tid);
    load_qtile(sb, g_Qh + base + (size_t)q_tile * QT * PD, tid);
    asm volatile("cp.async.wait_group 0;");
    __syncthreads();

    unsigned qf[4][4];
#pragma unroll
    for (int kk = 0; kk < 4; kk++)
        ldsm4(qf[kk][0], qf[kk][1], qf[kk][2], qf[kk][3],
              qrow_b + (unsigned)(((2 * kk + qao) ^ qsw) << 4));

    float acc[8][4];
#pragma unroll
    for (int nb = 0; nb < 8; nb++)
#pragma unroll
        for (int j = 0; j < 4; j++) acc[nb][j] = 0.f;
    float m0 = -1e30f, m1 = -1e30f, l0 = 0.f, l1 = 0.f;

    int stage = 0;
    for (int kt = 0; kt <= q_tile; kt++) {
        if (kt) {
            asm volatile("cp.async.wait_group 0;");
            __syncthreads();
        }
        if (kt < q_tile)
            load_stage(sb, stage ^ 1, Kg + (size_t)(kt + 1) * KT * PD,
                       Vg + (size_t)(kt + 1) * KT * PD, bg + (kt + 1) * KT, tid);

        const unsigned kb = sb + (stage ? SK1 : SK0);
        const unsigned vb = sb + (stage ? SV1 : SV0);
        const float* sB = (const float*)(sm + (stage ? SB1 : SB0));

        // ---- S = Q_aug @ K_aug^T (log2-units), C-init = pre-weighted bias ----
        float s[8][4];
#pragma unroll
        for (int nb = 0; nb < 8; nb++) {
            const float2 bb = *reinterpret_cast<const float2*>(sB + 8 * nb + 2 * c);
            s[nb][0] = bb.x; s[nb][1] = bb.y;
            s[nb][2] = bb.x; s[nb][3] = bb.y;
        }
#pragma unroll
        for (int kk = 0; kk < 4; kk++) {
#pragma unroll
            for (int A2 = 0; A2 < 4; A2++) {
                unsigned b0, b1, b2, b3;
                ldsm4(b0, b1, b2, b3,
                      kb + (unsigned)((16 * A2 + kr) * 128 + (((2 * kk + kao) ^ ksw) << 4)));
                mma16816(s[2*A2][0], s[2*A2][1], s[2*A2][2], s[2*A2][3],
                         qf[kk][0], qf[kk][1], qf[kk][2], qf[kk][3], b0, b1);
                mma16816(s[2*A2+1][0], s[2*A2+1][1], s[2*A2+1][2], s[2*A2+1][3],
                         qf[kk][0], qf[kk][1], qf[kk][2], qf[kk][3], b2, b3);
            }
        }

        if (kt == q_tile) {   // causal mask on the diagonal tile
            const int r0 = 16 * w + g, r1 = r0 + 8;
#pragma unroll
            for (int nb = 0; nb < 8; nb++) {
                const int k0 = 8 * nb + 2 * c, k1 = k0 + 1;
                if (k0 > r0) s[nb][0] = -1e30f;
                if (k1 > r0) s[nb][1] = -1e30f;
                if (k0 > r1) s[nb][2] = -1e30f;
                if (k1 > r1) s[nb][3] = -1e30f;
            }
        }

        // ---- online softmax (base-2) ----
        float rm0 = fmaxf(s[0][0], s[0][1]), rm1 = fmaxf(s[0][2], s[0][3]);
#pragma unroll
        for (int nb = 1; nb < 8; nb++) {
            rm0 = fmaxf(rm0, fmaxf(s[nb][0], s[nb][1]));
            rm1 = fmaxf(rm1, fmaxf(s[nb][2], s[nb][3]));
        }
        rm0 = fmaxf(rm0, __shfl_xor_sync(0xffffffffu, rm0, 1));
        rm0 = fmaxf(rm0, __shfl_xor_sync(0xffffffffu, rm0, 2));
        rm1 = fmaxf(rm1, __shfl_xor_sync(0xffffffffu, rm1, 1));
        rm1 = fmaxf(rm1, __shfl_xor_sync(0xffffffffu, rm1, 2));
        const float mn0 = fmaxf(m0, rm0), mn1 = fmaxf(m1, rm1);
        const float co0 = exp2f(m0 - mn0), co1 = exp2f(m1 - mn1);
        m0 = mn0; m1 = mn1;

        __syncwarp();   // previous PV ldmatrix reads done before P overwrite
        char* prow0 = sm + SPQ + (16 * w + g) * 128 + 4 * c;
        float rl0 = 0.f, rl1 = 0.f;
#pragma unroll
        for (int nb = 0; nb < 8; nb++) {
            const float p00 = exp2f(s[nb][0] - mn0);
            const float p01 = exp2f(s[nb][1] - mn0);
            const float p10 = exp2f(s[nb][2] - mn1);
            const float p11 = exp2f(s[nb][3] - mn1);
            rl0 += p00 + p01; rl1 += p10 + p11;
            const int atom = (nb ^ (g & 7)) << 4;
            *reinterpret_cast<__half2*>(prow0 + atom) = __floats2half2_rn(p00, p01);
            *reinterpret_cast<__half2*>(prow0 + 8 * 128 + atom) = __floats2half2_rn(p10, p11);
        }
        rl0 += __shfl_xor_sync(0xffffffffu, rl0, 1);
        rl0 += __shfl_xor_sync(0xffffffffu, rl0, 2);
        rl1 += __shfl_xor_sync(0xffffffffu, rl1, 1);
        rl1 += __shfl_xor_sync(0xffffffffu, rl1, 2);
        l0 = l0 * co0 + rl0;
        l1 = l1 * co1 + rl1;
#pragma unroll
        for (int nb = 0; nb < 8; nb++) {
            acc[nb][0] *= co0; acc[nb][1] *= co0;
            acc[nb][2] *= co1; acc[nb][3] *= co1;
        }
        __syncwarp();   // P fully written before ldmatrix reads

        // ---- O += P @ V ----
#pragma unroll
        for (int kk = 0; kk < 4; kk++) {
            unsigned a0, a1, a2, a3;
            ldsm4(a0, a1, a2, a3, qrow_b + (unsigned)(((2 * kk + qao) ^ qsw) << 4));
#pragma unroll
            for (int A2 = 0; A2 < 4; A2++) {
                unsigned b0, b1, b2, b3;
                ldsm4t(b0, b1, b2, b3,
                       vb + (unsigned)((16 * kk + vro) * 128 + (((2 * A2 + vao) ^ vsw) << 4)));
                mma16816(acc[2*A2][0], acc[2*A2][1], acc[2*A2][2], acc[2*A2][3],
                         a0, a1, a2, a3, b0, b1);
                mma16816(acc[2*A2+1][0], acc[2*A2+1][1], acc[2*A2+1][2], acc[2*A2+1][3],
                         a0, a1, a2, a3, b2, b3);
            }
        }
        stage ^= 1;
    }

    // ---- normalize + write ----
    const float inv0 = 1.0f / l0, inv1 = 1.0f / l1;
    float* og = out + base + ((size_t)q_tile * QT + 16 * w) * PD;
#pragma unroll
    for (int nb = 0; nb < 8; nb++) {
        *reinterpret_cast<float2*>(og + g * 64 + 8 * nb + 2 * c) =
            make_float2(acc[nb][0] * inv0, acc[nb][1] * inv0);
        *reinterpret_cast<float2*>(og + (g + 8) * 64 + 8 * nb + 2 * c) =
            make_float2(acc[nb][2] * inv1, acc[nb][3] * inv1);
    }
}

// ---------------------------------------------------------------------------
extern "C" void kernel_launch(void* const* d_in, const int* in_sizes, int n_in,
                              void* d_out, int out_size)
{
    const float* Q      = (const float*)d_in[0];
    const float* K      = (const float*)d_in[1];
    const float* V      = (const float*)d_in[2];
    const float* d_bias = (const float*)d_in[3];
    const float* W      = (const float*)d_in[4];
    const float* w_std  = (const float*)d_in[5];
    const float* w_rec  = (const float*)d_in[6];
    const float* w_disc = (const float*)d_in[7];
    float* out = (float*)d_out;

    cudaFuncSetAttribute(attn_kernel, cudaFuncAttributeMaxDynamicSharedMemorySize,
                         SMEM_BYTES);

    aug_kernel<<<PBH * PT / 4, 256>>>(Q, K, V, d_bias, W, w_std, w_rec, w_disc);

    dim3 grid(PT / QT, PBH);
    attn_kernel<<<grid, 128, SMEM_BYTES>>>(out);
}

// round 5
// speedup vs baseline: 5.8746x; 1.1099x over previous
#include <cuda_runtime.h>
#include <cuda_fp16.h>
#include <cstdint>

#define PB 2
#define PH 12
#define PT 2048
#define PD 64
#define PR 16
#define PD_STD 48
#define PBH (PB * PH)
#define QT 64
#define KT 64
#define LOG2E 1.4426950408889634f

// smem byte offsets (attn)
#define SK0 0
#define SK1 8192
#define SV0 16384
#define SV1 24576
#define SPQ 32768
#define SB0 40960
#define SB1 41216
#define SMEM_BYTES 41472

__device__ __half g_Qh[PBH * PT * PD];
__device__ __half g_Kh[PBH * PT * PD];
__device__ __half g_Vh[PBH * PT * PD];
__device__ float  g_bw[PBH * PT];

__device__ __forceinline__ void mma16816(float& d0, float& d1, float& d2, float& d3,
                                         unsigned a0, unsigned a1, unsigned a2, unsigned a3,
                                         unsigned b0, unsigned b1) {
    asm volatile(
        "mma.sync.aligned.m16n8k16.row.col.f32.f16.f16.f32 "
        "{%0,%1,%2,%3},{%4,%5,%6,%7},{%8,%9},{%0,%1,%2,%3};"
        : "+f"(d0), "+f"(d1), "+f"(d2), "+f"(d3)
        : "r"(a0), "r"(a1), "r"(a2), "r"(a3), "r"(b0), "r"(b1));
}
__device__ __forceinline__ void ldsm4(unsigned& r0, unsigned& r1, unsigned& r2, unsigned& r3,
                                      unsigned addr) {
    asm volatile("ldmatrix.sync.aligned.m8n8.x4.shared.b16 {%0,%1,%2,%3}, [%4];"
                 : "=r"(r0), "=r"(r1), "=r"(r2), "=r"(r3) : "r"(addr));
}
__device__ __forceinline__ void ldsm4t(unsigned& r0, unsigned& r1, unsigned& r2, unsigned& r3,
                                       unsigned addr) {
    asm volatile("ldmatrix.sync.aligned.m8n8.x4.trans.shared.b16 {%0,%1,%2,%3}, [%4];"
                 : "=r"(r0), "=r"(r1), "=r"(r2), "=r"(r3) : "r"(addr));
}
__device__ __forceinline__ void cpa16(unsigned dst, const void* src) {
    asm volatile("cp.async.cg.shared.global [%0], [%1], 16;" :: "r"(dst), "l"(src));
}
__device__ __forceinline__ float ex2(float x) {
    float y; asm("ex2.approx.ftz.f32 %0, %1;" : "=f"(y) : "f"(x)); return y;
}

// ---------------------------------------------------------------------------
// Fused prologue: fp16 Q_aug (0.125*log2e folded), fp16 K_aug, fp16 V,
// pre-weighted bias (log2e*w_disc folded). Block = 64 t-rows of one head.
// ---------------------------------------------------------------------------
#define AP 65
__global__ __launch_bounds__(256) void aug_kernel(
    const float* __restrict__ Q, const float* __restrict__ K,
    const float* __restrict__ V, const float* __restrict__ d_bias,
    const float* __restrict__ W,
    const float* __restrict__ w_std, const float* __restrict__ w_rec,
    const float* __restrict__ w_disc)
{
    __shared__ float sW[PD * PR];
    __shared__ float sQ[64 * AP];
    __shared__ float sK[64 * AP];
    __shared__ float sLQ[64 * 16];
    __shared__ float sLK[64 * 16];

    const int tid = threadIdx.x;
    const int bh  = blockIdx.y;
    const int h   = bh % PH;
    const int t0  = blockIdx.x * 64;
    const size_t gbase = ((size_t)bh * PT + t0) * PD;

    // phase A: stage W, Q, K
    for (int i = tid; i < PD * PR; i += 256) sW[i] = W[i];
#pragma unroll
    for (int k = 0; k < 16; k++) {
        const int i = tid + k * 256;
        const int t = i >> 6, d = i & 63;
        sQ[t * AP + d] = Q[gbase + i];
        sK[t * AP + d] = K[gbase + i];
    }
    __syncthreads();

    // phase B: low-rank projections
    {
        const int r = tid >> 2, c = tid & 3;
#pragma unroll
        for (int rr = 0; rr < 4; rr++) {
            const int rj = c * 4 + rr;
            float aq = 0.f, ak = 0.f;
#pragma unroll
            for (int j = 0; j < PD; j++) {
                aq = fmaf(sQ[r * AP + j], sW[j * PR + rj], aq);
                ak = fmaf(sK[r * AP + j], sW[j * PR + rj], ak);
            }
            sLQ[r * 16 + rj] = aq;
            sLK[r * 16 + rj] = ak;
        }
    }
    __syncthreads();

    // phase C: emit fp16 Q_aug / K_aug / V + bias (vectorized)
    {
        const float sstd = sqrtf(w_std[h]);
        const float srec = sqrtf(w_rec[h]);
        const float SCL = 0.125f * LOG2E;
        const int r = tid >> 2, d0 = (tid & 3) * 16;
        const size_t grow = gbase + (size_t)r * PD + d0;

        __half2 qo[8], ko[8], vo[8];
#pragma unroll
        for (int j = 0; j < 8; j++) {
            const int d = d0 + 2 * j;
            float q0, q1, k0, k1;
            if (d < PD_STD) {
                q0 = SCL * sstd * sQ[r * AP + d];   q1 = SCL * sstd * sQ[r * AP + d + 1];
                k0 = sstd * sK[r * AP + d];         k1 = sstd * sK[r * AP + d + 1];
            } else {
                const int rr = d - PD_STD;
                q0 = SCL * srec * sLK[r * 16 + rr]; q1 = SCL * srec * sLK[r * 16 + rr + 1];
                k0 = srec * sLQ[r * 16 + rr];       k1 = srec * sLQ[r * 16 + rr + 1];
            }
            qo[j] = __floats2half2_rn(q0, q1);
            ko[j] = __floats2half2_rn(k0, k1);
        }
#pragma unroll
        for (int j4 = 0; j4 < 4; j4++) {
            const float4 vv = *reinterpret_cast<const float4*>(&V[grow + 4 * j4]);
            vo[2 * j4]     = __floats2half2_rn(vv.x, vv.y);
            vo[2 * j4 + 1] = __floats2half2_rn(vv.z, vv.w);
        }
        *reinterpret_cast<uint4*>(&g_Qh[grow])     = *reinterpret_cast<uint4*>(&qo[0]);
        *reinterpret_cast<uint4*>(&g_Qh[grow + 8]) = *reinterpret_cast<uint4*>(&qo[4]);
        *reinterpret_cast<uint4*>(&g_Kh[grow])     = *reinterpret_cast<uint4*>(&ko[0]);
        *reinterpret_cast<uint4*>(&g_Kh[grow + 8]) = *reinterpret_cast<uint4*>(&ko[4]);
        *reinterpret_cast<uint4*>(&g_Vh[grow])     = *reinterpret_cast<uint4*>(&vo[0]);
        *reinterpret_cast<uint4*>(&g_Vh[grow + 8]) = *reinterpret_cast<uint4*>(&vo[4]);
        if (tid < 64)
            g_bw[(size_t)bh * PT + t0 + tid] =
                LOG2E * w_disc[h] * d_bias[(size_t)bh * PT + t0 + tid];
    }
}

// ---------------------------------------------------------------------------
// Swizzled fp16 tile loader (64 rows x 128B, SW128 xor swizzle) + f32 bias.
// ---------------------------------------------------------------------------
__device__ __forceinline__ void load_stage(unsigned sb, int stage,
                                           const __half* Kt, const __half* Vt,
                                           const float* bt, int tid)
{
    const unsigned kb = sb + (stage ? SK1 : SK0);
    const unsigned vb = sb + (stage ? SV1 : SV0);
    const unsigned bb = sb + (stage ? SB1 : SB0);
#pragma unroll
    for (int i = 0; i < 4; i++) {
        const int ch = tid + i * 128;
        const int r = ch >> 3, a = ch & 7;
        const unsigned off = (unsigned)(r * 128 + ((a ^ (r & 7)) << 4));
        cpa16(kb + off, Kt + r * 64 + a * 8);
        cpa16(vb + off, Vt + r * 64 + a * 8);
    }
    if (tid < 16) cpa16(bb + (unsigned)tid * 16u, bt + tid * 4);
    asm volatile("cp.async.commit_group;");
}

// ---------------------------------------------------------------------------
// Flash attention: fp16 HMMA.16816 + ldmatrix, P register-resident.
// CTA = (head, 64-row q-tile), 128 threads, 4 CTA/SM.
// ---------------------------------------------------------------------------
__global__ __launch_bounds__(128, 4) void attn_kernel(float* __restrict__ out)
{
    extern __shared__ char sm[];
    const unsigned sb = (unsigned)__cvta_generic_to_shared(sm);

    const int bh = blockIdx.y;
    const int q_tile = (PT / QT - 1) - blockIdx.x;   // heavy tiles first
    const size_t base = (size_t)bh * PT * PD;
    const __half* Kg = g_Kh + base;
    const __half* Vg = g_Vh + base;
    const float*  bg = g_bw + (size_t)bh * PT;

    const int tid = threadIdx.x;
    const int w = tid >> 5, lane = tid & 31;
    const int g = lane >> 2, c = lane & 3;

    // ldmatrix address components
    const int kr  = 8 * (lane >> 4) + (lane & 7);                 // K rows (B frag)
    const int kao = (lane >> 3) & 1;
    const int qr  = 16 * w + 8 * ((lane >> 3) & 1) + (lane & 7);  // Q rows (A frag)
    const int qao = lane >> 4;
    const int vro = 8 * ((lane >> 3) & 1) + (lane & 7);           // V rows (trans B)
    const int vao = lane >> 4;
    const unsigned qrow_b = sb + SPQ + (unsigned)qr * 128u;
    const int qsw = qr & 7, ksw = kr & 7, vsw = vro & 7;

    // stage0 K/V/bias + Q tile, then lift Q fragments
    load_stage(sb, 0, Kg, Vg, bg, tid);
    {
        const __half* Qt = g_Qh + base + (size_t)q_tile * QT * PD;
        const unsigned qb = sb + SPQ;
#pragma unroll
        for (int i = 0; i < 4; i++) {
            const int ch = tid + i * 128;
            const int r = ch >> 3, a = ch & 7;
            cpa16(qb + (unsigned)(r * 128 + ((a ^ (r & 7)) << 4)), Qt + r * 64 + a * 8);
        }
        asm volatile("cp.async.commit_group;");
    }
    asm volatile("cp.async.wait_group 0;");
    __syncthreads();

    unsigned qf[4][4];
#pragma unroll
    for (int kk = 0; kk < 4; kk++)
        ldsm4(qf[kk][0], qf[kk][1], qf[kk][2], qf[kk][3],
              qrow_b + (unsigned)(((2 * kk + qao) ^ qsw) << 4));

    float acc[8][4];
#pragma unroll
    for (int nb = 0; nb < 8; nb++)
#pragma unroll
        for (int j = 0; j < 4; j++) acc[nb][j] = 0.f;
    float m0 = -1e30f, m1 = -1e30f, l0 = 0.f, l1 = 0.f;

    int stage = 0;
    for (int kt = 0; kt <= q_tile; kt++) {
        if (kt) {
            asm volatile("cp.async.wait_group 0;");
            __syncthreads();
        }
        if (kt < q_tile)
            load_stage(sb, stage ^ 1, Kg + (size_t)(kt + 1) * KT * PD,
                       Vg + (size_t)(kt + 1) * KT * PD, bg + (kt + 1) * KT, tid);

        const unsigned kb = sb + (stage ? SK1 : SK0);
        const unsigned vb = sb + (stage ? SV1 : SV0);
        const float* sB = (const float*)(sm + (stage ? SB1 : SB0));

        // ---- S = Q @ K^T (log2 units), C-init = pre-weighted bias ----
        float s[8][4];
#pragma unroll
        for (int nb = 0; nb < 8; nb++) {
            const float2 bb = *reinterpret_cast<const float2*>(sB + 8 * nb + 2 * c);
            s[nb][0] = bb.x; s[nb][1] = bb.y;
            s[nb][2] = bb.x; s[nb][3] = bb.y;
        }
#pragma unroll
        for (int kk = 0; kk < 4; kk++) {
#pragma unroll
            for (int A2 = 0; A2 < 4; A2++) {
                unsigned b0, b1, b2, b3;
                ldsm4(b0, b1, b2, b3,
                      kb + (unsigned)((16 * A2 + kr) * 128 + (((2 * kk + kao) ^ ksw) << 4)));
                mma16816(s[2*A2][0], s[2*A2][1], s[2*A2][2], s[2*A2][3],
                         qf[kk][0], qf[kk][1], qf[kk][2], qf[kk][3], b0, b1);
                mma16816(s[2*A2+1][0], s[2*A2+1][1], s[2*A2+1][2], s[2*A2+1][3],
                         qf[kk][0], qf[kk][1], qf[kk][2], qf[kk][3], b2, b3);
            }
        }

        if (kt == q_tile) {   // causal mask on diagonal tile
            const int r0 = 16 * w + g, r1 = r0 + 8;
#pragma unroll
            for (int nb = 0; nb < 8; nb++) {
                const int k0 = 8 * nb + 2 * c, k1 = k0 + 1;
                if (k0 > r0) s[nb][0] = -1e30f;
                if (k1 > r0) s[nb][1] = -1e30f;
                if (k0 > r1) s[nb][2] = -1e30f;
                if (k1 > r1) s[nb][3] = -1e30f;
            }
        }

        // ---- online softmax (base-2), P packed directly into A fragments ----
        float rm0 = fmaxf(s[0][0], s[0][1]), rm1 = fmaxf(s[0][2], s[0][3]);
#pragma unroll
        for (int nb = 1; nb < 8; nb++) {
            rm0 = fmaxf(rm0, fmaxf(s[nb][0], s[nb][1]));
            rm1 = fmaxf(rm1, fmaxf(s[nb][2], s[nb][3]));
        }
        rm0 = fmaxf(rm0, __shfl_xor_sync(0xffffffffu, rm0, 1));
        rm0 = fmaxf(rm0, __shfl_xor_sync(0xffffffffu, rm0, 2));
        rm1 = fmaxf(rm1, __shfl_xor_sync(0xffffffffu, rm1, 1));
        rm1 = fmaxf(rm1, __shfl_xor_sync(0xffffffffu, rm1, 2));
        const float mn0 = fmaxf(m0, rm0), mn1 = fmaxf(m1, rm1);
        const float co0 = ex2(m0 - mn0), co1 = ex2(m1 - mn1);
        m0 = mn0; m1 = mn1;

        unsigned pk0[8], pk1[8];    // P fragments: rows g / g+8
        float rl0 = 0.f, rl1 = 0.f;
#pragma unroll
        for (int nb = 0; nb < 8; nb++) {
            const float p00 = ex2(s[nb][0] - mn0);
            const float p01 = ex2(s[nb][1] - mn0);
            const float p10 = ex2(s[nb][2] - mn1);
            const float p11 = ex2(s[nb][3] - mn1);
            rl0 += p00 + p01; rl1 += p10 + p11;
            const __half2 h0 = __floats2half2_rn(p00, p01);
            const __half2 h1 = __floats2half2_rn(p10, p11);
            pk0[nb] = *reinterpret_cast<const unsigned*>(&h0);
            pk1[nb] = *reinterpret_cast<const unsigned*>(&h1);
        }
        rl0 += __shfl_xor_sync(0xffffffffu, rl0, 1);
        rl0 += __shfl_xor_sync(0xffffffffu, rl0, 2);
        rl1 += __shfl_xor_sync(0xffffffffu, rl1, 1);
        rl1 += __shfl_xor_sync(0xffffffffu, rl1, 2);
        l0 = l0 * co0 + rl0;
        l1 = l1 * co1 + rl1;
#pragma unroll
        for (int nb = 0; nb < 8; nb++) {
            acc[nb][0] *= co0; acc[nb][1] *= co0;
            acc[nb][2] *= co1; acc[nb][3] *= co1;
        }

        // ---- O += P @ V (A from registers — no smem round trip) ----
#pragma unroll
        for (int kk = 0; kk < 4; kk++) {
            const unsigned a0 = pk0[2 * kk],     a1 = pk1[2 * kk];
            const unsigned a2 = pk0[2 * kk + 1], a3 = pk1[2 * kk + 1];
#pragma unroll
            for (int A2 = 0; A2 < 4; A2++) {
                unsigned b0, b1, b2, b3;
                ldsm4t(b0, b1, b2, b3,
                       vb + (unsigned)((16 * kk + vro) * 128 + (((2 * A2 + vao) ^ vsw) << 4)));
                mma16816(acc[2*A2][0], acc[2*A2][1], acc[2*A2][2], acc[2*A2][3],
                         a0, a1, a2, a3, b0, b1);
                mma16816(acc[2*A2+1][0], acc[2*A2+1][1], acc[2*A2+1][2], acc[2*A2+1][3],
                         a0, a1, a2, a3, b2, b3);
            }
        }
        stage ^= 1;
    }

    // ---- normalize + write ----
    const float inv0 = 1.0f / l0, inv1 = 1.0f / l1;
    float* og = out + base + ((size_t)q_tile * QT + 16 * w) * PD;
#pragma unroll
    for (int nb = 0; nb < 8; nb++) {
        *reinterpret_cast<float2*>(og + g * 64 + 8 * nb + 2 * c) =
            make_float2(acc[nb][0] * inv0, acc[nb][1] * inv0);
        *reinterpret_cast<float2*>(og + (g + 8) * 64 + 8 * nb + 2 * c) =
            make_float2(acc[nb][2] * inv1, acc[nb][3] * inv1);
    }
}

// ---------------------------------------------------------------------------
extern "C" void kernel_launch(void* const* d_in, const int* in_sizes, int n_in,
                              void* d_out, int out_size)
{
    const float* Q      = (const float*)d_in[0];
    const float* K      = (const float*)d_in[1];
    const float* V      = (const float*)d_in[2];
    const float* d_bias = (const float*)d_in[3];
    const float* W      = (const float*)d_in[4];
    const float* w_std  = (const float*)d_in[5];
    const float* w_rec  = (const float*)d_in[6];
    const float* w_disc = (const float*)d_in[7];
    float* out = (float*)d_out;

    cudaFuncSetAttribute(attn_kernel, cudaFuncAttributeMaxDynamicSharedMemorySize,
                         SMEM_BYTES);

    dim3 ag(PT / 64, PBH);
    aug_kernel<<<ag, 256>>>(Q, K, V, d_bias, W, w_std, w_rec, w_disc);

    dim3 grid(PT / QT, PBH);
    attn_kernel<<<grid, 128, SMEM_BYTES>>>(out);
}

// round 6
// speedup vs baseline: 6.1977x; 1.0550x over previous
#include <cuda_runtime.h>
#include <cuda_fp16.h>
#include <cstdint>

#define PB 2
#define PH 12
#define PT 2048
#define PD 64
#define PR 16
#define PD_STD 48
#define PBH (PB * PH)
#define QT 64
#define KT 128
#define LOG2E 1.4426950408889634f

// smem byte offsets (attn)
#define SQ  0          // Q tile 64x128B   = 8192
#define SK0 8192       // K tile 128x128B  = 16384
#define SK1 24576
#define SV0 40960      // V tile 128x128B  = 16384
#define SV1 57344
#define SB0 73728      // bias 128 f32 = 512
#define SB1 74240
#define SMEM_BYTES 74752

__device__ __half g_Qh[PBH * PT * PD];
__device__ __half g_Kh[PBH * PT * PD];
__device__ __half g_Vh[PBH * PT * PD];
__device__ float  g_bw[PBH * PT];

__device__ __forceinline__ void mma16816(float& d0, float& d1, float& d2, float& d3,
                                         unsigned a0, unsigned a1, unsigned a2, unsigned a3,
                                         unsigned b0, unsigned b1) {
    asm volatile(
        "mma.sync.aligned.m16n8k16.row.col.f32.f16.f16.f32 "
        "{%0,%1,%2,%3},{%4,%5,%6,%7},{%8,%9},{%0,%1,%2,%3};"
        : "+f"(d0), "+f"(d1), "+f"(d2), "+f"(d3)
        : "r"(a0), "r"(a1), "r"(a2), "r"(a3), "r"(b0), "r"(b1));
}
__device__ __forceinline__ void ldsm4(unsigned& r0, unsigned& r1, unsigned& r2, unsigned& r3,
                                      unsigned addr) {
    asm volatile("ldmatrix.sync.aligned.m8n8.x4.shared.b16 {%0,%1,%2,%3}, [%4];"
                 : "=r"(r0), "=r"(r1), "=r"(r2), "=r"(r3) : "r"(addr));
}
__device__ __forceinline__ void ldsm4t(unsigned& r0, unsigned& r1, unsigned& r2, unsigned& r3,
                                       unsigned addr) {
    asm volatile("ldmatrix.sync.aligned.m8n8.x4.trans.shared.b16 {%0,%1,%2,%3}, [%4];"
                 : "=r"(r0), "=r"(r1), "=r"(r2), "=r"(r3) : "r"(addr));
}
__device__ __forceinline__ void cpa16(unsigned dst, const void* src) {
    asm volatile("cp.async.cg.shared.global [%0], [%1], 16;" :: "r"(dst), "l"(src));
}
__device__ __forceinline__ float ex2(float x) {
    float y; asm("ex2.approx.ftz.f32 %0, %1;" : "=f"(y) : "f"(x)); return y;
}

// ---------------------------------------------------------------------------
// Fused prologue (unchanged from R5): fp16 Q_aug (0.125*log2e folded),
// fp16 K_aug, fp16 V, pre-weighted bias. Block = 64 t-rows of one head.
// ---------------------------------------------------------------------------
#define AP 65
__global__ __launch_bounds__(256) void aug_kernel(
    const float* __restrict__ Q, const float* __restrict__ K,
    const float* __restrict__ V, const float* __restrict__ d_bias,
    const float* __restrict__ W,
    const float* __restrict__ w_std, const float* __restrict__ w_rec,
    const float* __restrict__ w_disc)
{
    __shared__ float sW[PD * PR];
    __shared__ float sQ[64 * AP];
    __shared__ float sK[64 * AP];
    __shared__ float sLQ[64 * 16];
    __shared__ float sLK[64 * 16];

    const int tid = threadIdx.x;
    const int bh  = blockIdx.y;
    const int h   = bh % PH;
    const int t0  = blockIdx.x * 64;
    const size_t gbase = ((size_t)bh * PT + t0) * PD;

    for (int i = tid; i < PD * PR; i += 256) sW[i] = W[i];
#pragma unroll
    for (int k = 0; k < 16; k++) {
        const int i = tid + k * 256;
        const int t = i >> 6, d = i & 63;
        sQ[t * AP + d] = Q[gbase + i];
        sK[t * AP + d] = K[gbase + i];
    }
    __syncthreads();

    {
        const int r = tid >> 2, c = tid & 3;
#pragma unroll
        for (int rr = 0; rr < 4; rr++) {
            const int rj = c * 4 + rr;
            float aq = 0.f, ak = 0.f;
#pragma unroll
            for (int j = 0; j < PD; j++) {
                aq = fmaf(sQ[r * AP + j], sW[j * PR + rj], aq);
                ak = fmaf(sK[r * AP + j], sW[j * PR + rj], ak);
            }
            sLQ[r * 16 + rj] = aq;
            sLK[r * 16 + rj] = ak;
        }
    }
    __syncthreads();

    {
        const float sstd = sqrtf(w_std[h]);
        const float srec = sqrtf(w_rec[h]);
        const float SCL = 0.125f * LOG2E;
        const int r = tid >> 2, d0 = (tid & 3) * 16;
        const size_t grow = gbase + (size_t)r * PD + d0;

        __half2 qo[8], ko[8], vo[8];
#pragma unroll
        for (int j = 0; j < 8; j++) {
            const int d = d0 + 2 * j;
            float q0, q1, k0, k1;
            if (d < PD_STD) {
                q0 = SCL * sstd * sQ[r * AP + d];   q1 = SCL * sstd * sQ[r * AP + d + 1];
                k0 = sstd * sK[r * AP + d];         k1 = sstd * sK[r * AP + d + 1];
            } else {
                const int rr = d - PD_STD;
                q0 = SCL * srec * sLK[r * 16 + rr]; q1 = SCL * srec * sLK[r * 16 + rr + 1];
                k0 = srec * sLQ[r * 16 + rr];       k1 = srec * sLQ[r * 16 + rr + 1];
            }
            qo[j] = __floats2half2_rn(q0, q1);
            ko[j] = __floats2half2_rn(k0, k1);
        }
#pragma unroll
        for (int j4 = 0; j4 < 4; j4++) {
            const float4 vv = *reinterpret_cast<const float4*>(&V[grow + 4 * j4]);
            vo[2 * j4]     = __floats2half2_rn(vv.x, vv.y);
            vo[2 * j4 + 1] = __floats2half2_rn(vv.z, vv.w);
        }
        *reinterpret_cast<uint4*>(&g_Qh[grow])     = *reinterpret_cast<uint4*>(&qo[0]);
        *reinterpret_cast<uint4*>(&g_Qh[grow + 8]) = *reinterpret_cast<uint4*>(&qo[4]);
        *reinterpret_cast<uint4*>(&g_Kh[grow])     = *reinterpret_cast<uint4*>(&ko[0]);
        *reinterpret_cast<uint4*>(&g_Kh[grow + 8]) = *reinterpret_cast<uint4*>(&ko[4]);
        *reinterpret_cast<uint4*>(&g_Vh[grow])     = *reinterpret_cast<uint4*>(&vo[0]);
        *reinterpret_cast<uint4*>(&g_Vh[grow + 8]) = *reinterpret_cast<uint4*>(&vo[4]);
        if (tid < 64)
            g_bw[(size_t)bh * PT + t0 + tid] =
                LOG2E * w_disc[h] * d_bias[(size_t)bh * PT + t0 + tid];
    }
}

// ---------------------------------------------------------------------------
// 128-key stage loader (SW128 xor swizzle) + f32 bias.
// ---------------------------------------------------------------------------
__device__ __forceinline__ void load_stage(unsigned sb, int stage,
                                           const __half* Kt, const __half* Vt,
                                           const float* bt, int tid)
{
    const unsigned kb = sb + (stage ? SK1 : SK0);
    const unsigned vb = sb + (stage ? SV1 : SV0);
    const unsigned bb = sb + (stage ? SB1 : SB0);
#pragma unroll
    for (int i = 0; i < 8; i++) {
        const int ch = tid + i * 128;
        const int r = ch >> 3, a = ch & 7;
        const unsigned off = (unsigned)(r * 128 + ((a ^ (r & 7)) << 4));
        cpa16(kb + off, Kt + r * 64 + a * 8);
        cpa16(vb + off, Vt + r * 64 + a * 8);
    }
    if (tid < 32) cpa16(bb + (unsigned)tid * 16u, bt + tid * 4);
    asm volatile("cp.async.commit_group;");
}

// ---------------------------------------------------------------------------
// Flash attention: HMMA.16816, 128-key tiles, one softmax per 128 keys,
// P register-resident. CTA = (head, 64-row q-tile), 128 threads, 3 CTA/SM.
// ---------------------------------------------------------------------------
__global__ __launch_bounds__(128, 3) void attn_kernel(float* __restrict__ out)
{
    extern __shared__ char sm[];
    const unsigned sb = (unsigned)__cvta_generic_to_shared(sm);

    const int bh = blockIdx.y;
    const int q_tile = (PT / QT - 1) - blockIdx.x;   // heavy tiles first
    const int nkt = q_tile / 2 + 1;                  // 128-key tiles
    const size_t base = (size_t)bh * PT * PD;
    const __half* Kg = g_Kh + base;
    const __half* Vg = g_Vh + base;
    const float*  bg = g_bw + (size_t)bh * PT;

    const int tid = threadIdx.x;
    const int w = tid >> 5, lane = tid & 31;
    const int g = lane >> 2, c = lane & 3;

    // ldmatrix address components
    const int kr  = 8 * (lane >> 4) + (lane & 7);                 // K rows (B frag)
    const int kao = (lane >> 3) & 1;
    const int qr  = 16 * w + 8 * ((lane >> 3) & 1) + (lane & 7);  // Q rows (A frag)
    const int qao = lane >> 4;
    const int vro = 8 * ((lane >> 3) & 1) + (lane & 7);           // V rows (trans B)
    const int vao = lane >> 4;
    const unsigned qrow_b = sb + SQ + (unsigned)qr * 128u;
    const int qsw = qr & 7, ksw = kr & 7, vsw = vro & 7;
    const int grow0 = q_tile * QT + 16 * w + g;      // this lane's first q row

    // stage0 K/V/bias + Q tile
    load_stage(sb, 0, Kg, Vg, bg, tid);
    {
        const __half* Qt = g_Qh + base + (size_t)q_tile * QT * PD;
#pragma unroll
        for (int i = 0; i < 4; i++) {
            const int ch = tid + i * 128;
            const int r = ch >> 3, a = ch & 7;
            cpa16(sb + SQ + (unsigned)(r * 128 + ((a ^ (r & 7)) << 4)), Qt + r * 64 + a * 8);
        }
        asm volatile("cp.async.commit_group;");
    }
    asm volatile("cp.async.wait_group 0;");
    __syncthreads();

    unsigned qf[4][4];
#pragma unroll
    for (int kk = 0; kk < 4; kk++)
        ldsm4(qf[kk][0], qf[kk][1], qf[kk][2], qf[kk][3],
              qrow_b + (unsigned)(((2 * kk + qao) ^ qsw) << 4));

    float acc[8][4];
#pragma unroll
    for (int nb = 0; nb < 8; nb++)
#pragma unroll
        for (int j = 0; j < 4; j++) acc[nb][j] = 0.f;
    float m0 = -1e30f, m1 = -1e30f, l0 = 0.f, l1 = 0.f;

    int stage = 0;
    for (int kt = 0; kt < nkt; kt++) {
        if (kt) {
            asm volatile("cp.async.wait_group 0;");
            __syncthreads();
        }
        if (kt + 1 < nkt)
            load_stage(sb, stage ^ 1, Kg + (size_t)(kt + 1) * KT * PD,
                       Vg + (size_t)(kt + 1) * KT * PD, bg + (kt + 1) * KT, tid);

        const unsigned kb = sb + (stage ? SK1 : SK0);
        const unsigned vb = sb + (stage ? SV1 : SV0);
        const float* sB = (const float*)(sm + (stage ? SB1 : SB0));

        // ---- S (16x128 per warp): C-init = pre-weighted bias ----
        float s[16][4];
#pragma unroll
        for (int nb = 0; nb < 16; nb++) {
            const float2 bb = *reinterpret_cast<const float2*>(sB + 8 * nb + 2 * c);
            s[nb][0] = bb.x; s[nb][1] = bb.y;
            s[nb][2] = bb.x; s[nb][3] = bb.y;
        }
#pragma unroll
        for (int kk = 0; kk < 4; kk++) {
#pragma unroll
            for (int A2 = 0; A2 < 8; A2++) {
                unsigned b0, b1, b2, b3;
                ldsm4(b0, b1, b2, b3,
                      kb + (unsigned)((16 * A2 + kr) * 128 + (((2 * kk + kao) ^ ksw) << 4)));
                mma16816(s[2*A2][0], s[2*A2][1], s[2*A2][2], s[2*A2][3],
                         qf[kk][0], qf[kk][1], qf[kk][2], qf[kk][3], b0, b1);
                mma16816(s[2*A2+1][0], s[2*A2+1][1], s[2*A2+1][2], s[2*A2+1][3],
                         qf[kk][0], qf[kk][1], qf[kk][2], qf[kk][3], b2, b3);
            }
        }

        if (kt == nkt - 1) {   // causal mask, last 128-key tile
            const int kk0 = grow0 - kt * KT;        // local key bound, row g
#pragma unroll
            for (int nb = 0; nb < 16; nb++) {
                const int j0 = 8 * nb + 2 * c, j1 = j0 + 1;
                if (j0 > kk0)     s[nb][0] = -1e30f;
                if (j1 > kk0)     s[nb][1] = -1e30f;
                if (j0 > kk0 + 8) s[nb][2] = -1e30f;
                if (j1 > kk0 + 8) s[nb][3] = -1e30f;
            }
        }

        // ---- softmax over 128 keys (base-2) ----
        float rm0 = fmaxf(s[0][0], s[0][1]), rm1 = fmaxf(s[0][2], s[0][3]);
#pragma unroll
        for (int nb = 1; nb < 16; nb++) {
            rm0 = fmaxf(rm0, fmaxf(s[nb][0], s[nb][1]));
            rm1 = fmaxf(rm1, fmaxf(s[nb][2], s[nb][3]));
        }
        rm0 = fmaxf(rm0, __shfl_xor_sync(0xffffffffu, rm0, 1));
        rm0 = fmaxf(rm0, __shfl_xor_sync(0xffffffffu, rm0, 2));
        rm1 = fmaxf(rm1, __shfl_xor_sync(0xffffffffu, rm1, 1));
        rm1 = fmaxf(rm1, __shfl_xor_sync(0xffffffffu, rm1, 2));
        const float mn0 = fmaxf(m0, rm0), mn1 = fmaxf(m1, rm1);
        const float co0 = ex2(m0 - mn0), co1 = ex2(m1 - mn1);
        const bool moved = (mn0 > m0) | (mn1 > m1);
        m0 = mn0; m1 = mn1;

        unsigned pk0[16], pk1[16];
        float rl0 = 0.f, rl1 = 0.f;
#pragma unroll
        for (int nb = 0; nb < 16; nb++) {
            const float p00 = ex2(s[nb][0] - mn0);
            const float p01 = ex2(s[nb][1] - mn0);
            const float p10 = ex2(s[nb][2] - mn1);
            const float p11 = ex2(s[nb][3] - mn1);
            rl0 += p00 + p01; rl1 += p10 + p11;
            const __half2 h0 = __floats2half2_rn(p00, p01);
            const __half2 h1 = __floats2half2_rn(p10, p11);
            pk0[nb] = *reinterpret_cast<const unsigned*>(&h0);
            pk1[nb] = *reinterpret_cast<const unsigned*>(&h1);
        }
        rl0 += __shfl_xor_sync(0xffffffffu, rl0, 1);
        rl0 += __shfl_xor_sync(0xffffffffu, rl0, 2);
        rl1 += __shfl_xor_sync(0xffffffffu, rl1, 1);
        rl1 += __shfl_xor_sync(0xffffffffu, rl1, 2);
        l0 = l0 * co0 + rl0;
        l1 = l1 * co1 + rl1;

        if (__ballot_sync(0xffffffffu, moved)) {     // skip rescale when max stable
#pragma unroll
            for (int nb = 0; nb < 8; nb++) {
                acc[nb][0] *= co0; acc[nb][1] *= co0;
                acc[nb][2] *= co1; acc[nb][3] *= co1;
            }
        }

        // ---- O += P @ V (A fragments from registers) ----
#pragma unroll
        for (int kk = 0; kk < 8; kk++) {
            const unsigned a0 = pk0[2 * kk],     a1 = pk1[2 * kk];
            const unsigned a2 = pk0[2 * kk + 1], a3 = pk1[2 * kk + 1];
#pragma unroll
            for (int A2 = 0; A2 < 4; A2++) {
                unsigned b0, b1, b2, b3;
                ldsm4t(b0, b1, b2, b3,
                       vb + (unsigned)((16 * kk + vro) * 128 + (((2 * A2 + vao) ^ vsw) << 4)));
                mma16816(acc[2*A2][0], acc[2*A2][1], acc[2*A2][2], acc[2*A2][3],
                         a0, a1, a2, a3, b0, b1);
                mma16816(acc[2*A2+1][0], acc[2*A2+1][1], acc[2*A2+1][2], acc[2*A2+1][3],
                         a0, a1, a2, a3, b2, b3);
            }
        }
        stage ^= 1;
    }

    // ---- normalize + write ----
    const float inv0 = 1.0f / l0, inv1 = 1.0f / l1;
    float* og = out + base + ((size_t)q_tile * QT + 16 * w) * PD;
#pragma unroll
    for (int nb = 0; nb < 8; nb++) {
        *reinterpret_cast<float2*>(og + g * 64 + 8 * nb + 2 * c) =
            make_float2(acc[nb][0] * inv0, acc[nb][1] * inv0);
        *reinterpret_cast<float2*>(og + (g + 8) * 64 + 8 * nb + 2 * c) =
            make_float2(acc[nb][2] * inv1, acc[nb][3] * inv1);
    }
}

// ---------------------------------------------------------------------------
extern "C" void kernel_launch(void* const* d_in, const int* in_sizes, int n_in,
                              void* d_out, int out_size)
{
    const float* Q      = (const float*)d_in[0];
    const float* K      = (const float*)d_in[1];
    const float* V      = (const float*)d_in[2];
    const float* d_bias = (const float*)d_in[3];
    const float* W      = (const float*)d_in[4];
    const float* w_std  = (const float*)d_in[5];
    const float* w_rec  = (const float*)d_in[6];
    const float* w_disc = (const float*)d_in[7];
    float* out = (float*)d_out;

    cudaFuncSetAttribute(attn_kernel, cudaFuncAttributeMaxDynamicSharedMemorySize,
                         SMEM_BYTES);

    dim3 ag(PT / 64, PBH);
    aug_kernel<<<ag, 256>>>(Q, K, V, d_bias, W, w_std, w_rec, w_disc);

    dim3 grid(PT / QT, PBH);
    attn_kernel<<<grid, 128, SMEM_BYTES>>>(out);
}

// round 7
// speedup vs baseline: 6.2000x; 1.0004x over previous
#include <cuda_runtime.h>
#include <cuda_fp16.h>
#include <cstdint>

#define PB 2
#define PH 12
#define PT 2048
#define PD 64
#define PR 16
#define PD_STD 48
#define PBH (PB * PH)
#define QT 64
#define KT 128
#define LOG2E 1.4426950408889634f

// smem byte offsets (attn)
#define SQ  0          // Q tile 64x128B   = 8192
#define SK0 8192       // K tile 128x128B  = 16384
#define SK1 24576
#define SV0 40960      // V tile 128x128B  = 16384
#define SV1 57344
#define SB0 73728      // bias 128 f32 = 512
#define SB1 74240
#define SMEM_BYTES 74752

__device__ __half g_Qh[PBH * PT * PD];
__device__ __half g_Kh[PBH * PT * PD];
__device__ __half g_Vh[PBH * PT * PD];
__device__ float  g_bw[PBH * PT];

__device__ __forceinline__ void mma16816(float& d0, float& d1, float& d2, float& d3,
                                         unsigned a0, unsigned a1, unsigned a2, unsigned a3,
                                         unsigned b0, unsigned b1) {
    asm volatile(
        "mma.sync.aligned.m16n8k16.row.col.f32.f16.f16.f32 "
        "{%0,%1,%2,%3},{%4,%5,%6,%7},{%8,%9},{%0,%1,%2,%3};"
        : "+f"(d0), "+f"(d1), "+f"(d2), "+f"(d3)
        : "r"(a0), "r"(a1), "r"(a2), "r"(a3), "r"(b0), "r"(b1));
}
__device__ __forceinline__ void ldsm4(unsigned& r0, unsigned& r1, unsigned& r2, unsigned& r3,
                                      unsigned addr) {
    asm volatile("ldmatrix.sync.aligned.m8n8.x4.shared.b16 {%0,%1,%2,%3}, [%4];"
                 : "=r"(r0), "=r"(r1), "=r"(r2), "=r"(r3) : "r"(addr));
}
__device__ __forceinline__ void ldsm4t(unsigned& r0, unsigned& r1, unsigned& r2, unsigned& r3,
                                       unsigned addr) {
    asm volatile("ldmatrix.sync.aligned.m8n8.x4.trans.shared.b16 {%0,%1,%2,%3}, [%4];"
                 : "=r"(r0), "=r"(r1), "=r"(r2), "=r"(r3) : "r"(addr));
}
__device__ __forceinline__ void cpa16(unsigned dst, const void* src) {
    asm volatile("cp.async.cg.shared.global [%0], [%1], 16;" :: "r"(dst), "l"(src));
}
__device__ __forceinline__ float ex2(float x) {
    float y; asm("ex2.approx.ftz.f32 %0, %1;" : "=f"(y) : "f"(x)); return y;
}
// packed fp16 exp2: argument (f32 pair) -> half2 -> MUFU f16x2
__device__ __forceinline__ unsigned ex2_pk(float x0, float x1) {
    const __half2 h = __floats2half2_rn(x0, x1);
    unsigned y;
    asm("ex2.approx.f16x2 %0, %1;" : "=r"(y) : "r"(*reinterpret_cast<const unsigned*>(&h)));
    return y;
}

// ---------------------------------------------------------------------------
// Fused prologue: fp16 Q_aug (0.125*log2e folded), fp16 K_aug, fp16 V,
// pre-weighted bias (log2e*w_disc folded). Block = 64 t-rows of one head.
// ---------------------------------------------------------------------------
#define AP 65
__global__ __launch_bounds__(256) void aug_kernel(
    const float* __restrict__ Q, const float* __restrict__ K,
    const float* __restrict__ V, const float* __restrict__ d_bias,
    const float* __restrict__ W,
    const float* __restrict__ w_std, const float* __restrict__ w_rec,
    const float* __restrict__ w_disc)
{
    __shared__ float sW[PD * PR];
    __shared__ float sQ[64 * AP];
    __shared__ float sK[64 * AP];
    __shared__ float sLQ[64 * 16];
    __shared__ float sLK[64 * 16];

    const int tid = threadIdx.x;
    const int bh  = blockIdx.y;
    const int h   = bh % PH;
    const int t0  = blockIdx.x * 64;
    const size_t gbase = ((size_t)bh * PT + t0) * PD;

    for (int i = tid; i < PD * PR; i += 256) sW[i] = W[i];
#pragma unroll
    for (int k = 0; k < 16; k++) {
        const int i = tid + k * 256;
        const int t = i >> 6, d = i & 63;
        sQ[t * AP + d] = Q[gbase + i];
        sK[t * AP + d] = K[gbase + i];
    }
    __syncthreads();

    {
        const int r = tid >> 2, c = tid & 3;
#pragma unroll
        for (int rr = 0; rr < 4; rr++) {
            const int rj = c * 4 + rr;
            float aq = 0.f, ak = 0.f;
#pragma unroll
            for (int j = 0; j < PD; j++) {
                aq = fmaf(sQ[r * AP + j], sW[j * PR + rj], aq);
                ak = fmaf(sK[r * AP + j], sW[j * PR + rj], ak);
            }
            sLQ[r * 16 + rj] = aq;
            sLK[r * 16 + rj] = ak;
        }
    }
    __syncthreads();

    {
        const float sstd = sqrtf(w_std[h]);
        const float srec = sqrtf(w_rec[h]);
        const float SCL = 0.125f * LOG2E;
        const int r = tid >> 2, d0 = (tid & 3) * 16;
        const size_t grow = gbase + (size_t)r * PD + d0;

        __half2 qo[8], ko[8], vo[8];
#pragma unroll
        for (int j = 0; j < 8; j++) {
            const int d = d0 + 2 * j;
            float q0, q1, k0, k1;
            if (d < PD_STD) {
                q0 = SCL * sstd * sQ[r * AP + d];   q1 = SCL * sstd * sQ[r * AP + d + 1];
                k0 = sstd * sK[r * AP + d];         k1 = sstd * sK[r * AP + d + 1];
            } else {
                const int rr = d - PD_STD;
                q0 = SCL * srec * sLK[r * 16 + rr]; q1 = SCL * srec * sLK[r * 16 + rr + 1];
                k0 = srec * sLQ[r * 16 + rr];       k1 = srec * sLQ[r * 16 + rr + 1];
            }
            qo[j] = __floats2half2_rn(q0, q1);
            ko[j] = __floats2half2_rn(k0, k1);
        }
#pragma unroll
        for (int j4 = 0; j4 < 4; j4++) {
            const float4 vv = *reinterpret_cast<const float4*>(&V[grow + 4 * j4]);
            vo[2 * j4]     = __floats2half2_rn(vv.x, vv.y);
            vo[2 * j4 + 1] = __floats2half2_rn(vv.z, vv.w);
        }
        *reinterpret_cast<uint4*>(&g_Qh[grow])     = *reinterpret_cast<uint4*>(&qo[0]);
        *reinterpret_cast<uint4*>(&g_Qh[grow + 8]) = *reinterpret_cast<uint4*>(&qo[4]);
        *reinterpret_cast<uint4*>(&g_Kh[grow])     = *reinterpret_cast<uint4*>(&ko[0]);
        *reinterpret_cast<uint4*>(&g_Kh[grow + 8]) = *reinterpret_cast<uint4*>(&ko[4]);
        *reinterpret_cast<uint4*>(&g_Vh[grow])     = *reinterpret_cast<uint4*>(&vo[0]);
        *reinterpret_cast<uint4*>(&g_Vh[grow + 8]) = *reinterpret_cast<uint4*>(&vo[4]);
        if (tid < 64)
            g_bw[(size_t)bh * PT + t0 + tid] =
                LOG2E * w_disc[h] * d_bias[(size_t)bh * PT + t0 + tid];
    }
}

// ---------------------------------------------------------------------------
// 128-key stage loader (SW128 xor swizzle) + f32 bias.
// ---------------------------------------------------------------------------
__device__ __forceinline__ void load_stage(unsigned sb, int stage,
                                           const __half* Kt, const __half* Vt,
                                           const float* bt, int tid)
{
    const unsigned kb = sb + (stage ? SK1 : SK0);
    const unsigned vb = sb + (stage ? SV1 : SV0);
    const unsigned bb = sb + (stage ? SB1 : SB0);
#pragma unroll
    for (int i = 0; i < 8; i++) {
        const int ch = tid + i * 128;
        const int r = ch >> 3, a = ch & 7;
        const unsigned off = (unsigned)(r * 128 + ((a ^ (r & 7)) << 4));
        cpa16(kb + off, Kt + r * 64 + a * 8);
        cpa16(vb + off, Vt + r * 64 + a * 8);
    }
    if (tid < 32) cpa16(bb + (unsigned)tid * 16u, bt + tid * 4);
    asm volatile("cp.async.commit_group;");
}

// ---------------------------------------------------------------------------
// Flash attention: HMMA.16816, 128-key tiles, packed-fp16 exp,
// row-sums via ones-column MMA. CTA = (head, 64-row q-tile), 128 thr, 3/SM.
// ---------------------------------------------------------------------------
__global__ __launch_bounds__(128, 3) void attn_kernel(float* __restrict__ out)
{
    extern __shared__ char sm[];
    const unsigned sb = (unsigned)__cvta_generic_to_shared(sm);

    const int bh = blockIdx.y;
    const int q_tile = (PT / QT - 1) - blockIdx.x;   // heavy tiles first
    const int nkt = q_tile / 2 + 1;                  // 128-key tiles
    const size_t base = (size_t)bh * PT * PD;
    const __half* Kg = g_Kh + base;
    const __half* Vg = g_Vh + base;
    const float*  bg = g_bw + (size_t)bh * PT;

    const int tid = threadIdx.x;
    const int w = tid >> 5, lane = tid & 31;
    const int g = lane >> 2, c = lane & 3;

    // ldmatrix address components
    const int kr  = 8 * (lane >> 4) + (lane & 7);                 // K rows (B frag)
    const int kao = (lane >> 3) & 1;
    const int qr  = 16 * w + 8 * ((lane >> 3) & 1) + (lane & 7);  // Q rows (A frag)
    const int qao = lane >> 4;
    const int vro = 8 * ((lane >> 3) & 1) + (lane & 7);           // V rows (trans B)
    const int vao = lane >> 4;
    const unsigned qrow_b = sb + SQ + (unsigned)qr * 128u;
    const int qsw = qr & 7, ksw = kr & 7, vsw = vro & 7;
    const int grow0 = q_tile * QT + 16 * w + g;      // this lane's first q row

    // stage0 K/V/bias + Q tile
    load_stage(sb, 0, Kg, Vg, bg, tid);
    {
        const __half* Qt = g_Qh + base + (size_t)q_tile * QT * PD;
#pragma unroll
        for (int i = 0; i < 4; i++) {
            const int ch = tid + i * 128;
            const int r = ch >> 3, a = ch & 7;
            cpa16(sb + SQ + (unsigned)(r * 128 + ((a ^ (r & 7)) << 4)), Qt + r * 64 + a * 8);
        }
        asm volatile("cp.async.commit_group;");
    }
    asm volatile("cp.async.wait_group 0;");
    __syncthreads();

    unsigned qf[4][4];
#pragma unroll
    for (int kk = 0; kk < 4; kk++)
        ldsm4(qf[kk][0], qf[kk][1], qf[kk][2], qf[kk][3],
              qrow_b + (unsigned)(((2 * kk + qao) ^ qsw) << 4));

    float acc[8][4];
#pragma unroll
    for (int nb = 0; nb < 8; nb++)
#pragma unroll
        for (int j = 0; j < 4; j++) acc[nb][j] = 0.f;
    float accl[4] = {0.f, 0.f, 0.f, 0.f};            // P row sums (ones-column mma)
    float m0 = -1e30f, m1 = -1e30f;

    int stage = 0;
    for (int kt = 0; kt < nkt; kt++) {
        if (kt) {
            asm volatile("cp.async.wait_group 0;");
            __syncthreads();
        }
        if (kt + 1 < nkt)
            load_stage(sb, stage ^ 1, Kg + (size_t)(kt + 1) * KT * PD,
                       Vg + (size_t)(kt + 1) * KT * PD, bg + (kt + 1) * KT, tid);

        const unsigned kb = sb + (stage ? SK1 : SK0);
        const unsigned vb = sb + (stage ? SV1 : SV0);
        const float* sB = (const float*)(sm + (stage ? SB1 : SB0));

        // ---- S (16x128 per warp): C-init = pre-weighted bias ----
        float s[16][4];
#pragma unroll
        for (int nb = 0; nb < 16; nb++) {
            const float2 bb = *reinterpret_cast<const float2*>(sB + 8 * nb + 2 * c);
            s[nb][0] = bb.x; s[nb][1] = bb.y;
            s[nb][2] = bb.x; s[nb][3] = bb.y;
        }
#pragma unroll
        for (int kk = 0; kk < 4; kk++) {
#pragma unroll
            for (int A2 = 0; A2 < 8; A2++) {
                unsigned b0, b1, b2, b3;
                ldsm4(b0, b1, b2, b3,
                      kb + (unsigned)((16 * A2 + kr) * 128 + (((2 * kk + kao) ^ ksw) << 4)));
                mma16816(s[2*A2][0], s[2*A2][1], s[2*A2][2], s[2*A2][3],
                         qf[kk][0], qf[kk][1], qf[kk][2], qf[kk][3], b0, b1);
                mma16816(s[2*A2+1][0], s[2*A2+1][1], s[2*A2+1][2], s[2*A2+1][3],
                         qf[kk][0], qf[kk][1], qf[kk][2], qf[kk][3], b2, b3);
            }
        }

        if (kt == nkt - 1) {   // causal mask, last 128-key tile
            const int kk0 = grow0 - kt * KT;        // local key bound, row g
#pragma unroll
            for (int nb = 0; nb < 16; nb++) {
                const int j0 = 8 * nb + 2 * c, j1 = j0 + 1;
                if (j0 > kk0)     s[nb][0] = -1e30f;
                if (j1 > kk0)     s[nb][1] = -1e30f;
                if (j0 > kk0 + 8) s[nb][2] = -1e30f;
                if (j1 > kk0 + 8) s[nb][3] = -1e30f;
            }
        }

        // ---- softmax over 128 keys: f32 max, packed fp16 exp ----
        float rm0 = fmaxf(s[0][0], s[0][1]), rm1 = fmaxf(s[0][2], s[0][3]);
#pragma unroll
        for (int nb = 1; nb < 16; nb++) {
            rm0 = fmaxf(rm0, fmaxf(s[nb][0], s[nb][1]));
            rm1 = fmaxf(rm1, fmaxf(s[nb][2], s[nb][3]));
        }
        rm0 = fmaxf(rm0, __shfl_xor_sync(0xffffffffu, rm0, 1));
        rm0 = fmaxf(rm0, __shfl_xor_sync(0xffffffffu, rm0, 2));
        rm1 = fmaxf(rm1, __shfl_xor_sync(0xffffffffu, rm1, 1));
        rm1 = fmaxf(rm1, __shfl_xor_sync(0xffffffffu, rm1, 2));
        const float mn0 = fmaxf(m0, rm0), mn1 = fmaxf(m1, rm1);
        const float co0 = ex2(m0 - mn0), co1 = ex2(m1 - mn1);
        const bool moved = (mn0 > m0) | (mn1 > m1);
        m0 = mn0; m1 = mn1;

        unsigned pk0[16], pk1[16];   // P fragments, exp done in fp16x2 MUFU
#pragma unroll
        for (int nb = 0; nb < 16; nb++) {
            pk0[nb] = ex2_pk(s[nb][0] - mn0, s[nb][1] - mn0);
            pk1[nb] = ex2_pk(s[nb][2] - mn1, s[nb][3] - mn1);
        }

        if (__ballot_sync(0xffffffffu, moved)) {     // skip rescale when max stable
#pragma unroll
            for (int nb = 0; nb < 8; nb++) {
                acc[nb][0] *= co0; acc[nb][1] *= co0;
                acc[nb][2] *= co1; acc[nb][3] *= co1;
            }
            accl[0] *= co0; accl[1] *= co0;
            accl[2] *= co1; accl[3] *= co1;
        }

        // ---- O += P @ V; row sums via all-ones B fragment ----
        const unsigned ONES = 0x3C003C00u;
#pragma unroll
        for (int kk = 0; kk < 8; kk++) {
            const unsigned a0 = pk0[2 * kk],     a1 = pk1[2 * kk];
            const unsigned a2 = pk0[2 * kk + 1], a3 = pk1[2 * kk + 1];
#pragma unroll
            for (int A2 = 0; A2 < 4; A2++) {
                unsigned b0, b1, b2, b3;
                ldsm4t(b0, b1, b2, b3,
                       vb + (unsigned)((16 * kk + vro) * 128 + (((2 * A2 + vao) ^ vsw) << 4)));
                mma16816(acc[2*A2][0], acc[2*A2][1], acc[2*A2][2], acc[2*A2][3],
                         a0, a1, a2, a3, b0, b1);
                mma16816(acc[2*A2+1][0], acc[2*A2+1][1], acc[2*A2+1][2], acc[2*A2+1][3],
                         a0, a1, a2, a3, b2, b3);
            }
            mma16816(accl[0], accl[1], accl[2], accl[3], a0, a1, a2, a3, ONES, ONES);
        }
        stage ^= 1;
    }

    // ---- normalize + write (accl[0]=row g sum, accl[2]=row g+8 sum) ----
    const float inv0 = 1.0f / accl[0], inv1 = 1.0f / accl[2];
    float* og = out + base + ((size_t)q_tile * QT + 16 * w) * PD;
#pragma unroll
    for (int nb = 0; nb < 8; nb++) {
        *reinterpret_cast<float2*>(og + g * 64 + 8 * nb + 2 * c) =
            make_float2(acc[nb][0] * inv0, acc[nb][1] * inv0);
        *reinterpret_cast<float2*>(og + (g + 8) * 64 + 8 * nb + 2 * c) =
            make_float2(acc[nb][2] * inv1, acc[nb][3] * inv1);
    }
}

// ---------------------------------------------------------------------------
extern "C" void kernel_launch(void* const* d_in, const int* in_sizes, int n_in,
                              void* d_out, int out_size)
{
    const float* Q      = (const float*)d_in[0];
    const float* K      = (const float*)d_in[1];
    const float* V      = (const float*)d_in[2];
    const float* d_bias = (const float*)d_in[3];
    const float* W      = (const float*)d_in[4];
    const float* w_std  = (const float*)d_in[5];
    const float* w_rec  = (const float*)d_in[6];
    const float* w_disc = (const float*)d_in[7];
    float* out = (float*)d_out;

    cudaFuncSetAttribute(attn_kernel, cudaFuncAttributeMaxDynamicSharedMemorySize,
                         SMEM_BYTES);

    dim3 ag(PT / 64, PBH);
    aug_kernel<<<ag, 256>>>(Q, K, V, d_bias, W, w_std, w_rec, w_disc);

    dim3 grid(PT / QT, PBH);
    attn_kernel<<<grid, 128, SMEM_BYTES>>>(out);
}

// round 8
// speedup vs baseline: 6.8269x; 1.1011x over previous
#include <cuda_runtime.h>
#include <cuda_fp16.h>
#include <cstdint>

#define PB 2
#define PH 12
#define PT 2048
#define PD 64
#define PR 16
#define PD_STD 48
#define PBH (PB * PH)
#define QT 64
#define KT 128
#define LOG2E 1.4426950408889634f

// smem byte offsets (attn)
#define SQ  0          // Q tile 64x128B   = 8192
#define SK0 8192       // K tile 128x128B  = 16384
#define SK1 24576
#define SV0 40960      // V tile 128x128B  = 16384
#define SV1 57344
#define SB0 73728      // bias 128 f32 = 512
#define SB1 74240
#define SMEM_BYTES 74752

__device__ __half g_Qh[PBH * PT * PD];
__device__ __half g_Kh[PBH * PT * PD];
__device__ __half g_Vh[PBH * PT * PD];
__device__ float  g_bw[PBH * PT];

__device__ __forceinline__ void mma16816(float& d0, float& d1, float& d2, float& d3,
                                         unsigned a0, unsigned a1, unsigned a2, unsigned a3,
                                         unsigned b0, unsigned b1) {
    asm volatile(
        "mma.sync.aligned.m16n8k16.row.col.f32.f16.f16.f32 "
        "{%0,%1,%2,%3},{%4,%5,%6,%7},{%8,%9},{%0,%1,%2,%3};"
        : "+f"(d0), "+f"(d1), "+f"(d2), "+f"(d3)
        : "r"(a0), "r"(a1), "r"(a2), "r"(a3), "r"(b0), "r"(b1));
}
__device__ __forceinline__ void ldsm4(unsigned& r0, unsigned& r1, unsigned& r2, unsigned& r3,
                                      unsigned addr) {
    asm volatile("ldmatrix.sync.aligned.m8n8.x4.shared.b16 {%0,%1,%2,%3}, [%4];"
                 : "=r"(r0), "=r"(r1), "=r"(r2), "=r"(r3) : "r"(addr));
}
__device__ __forceinline__ void ldsm4t(unsigned& r0, unsigned& r1, unsigned& r2, unsigned& r3,
                                       unsigned addr) {
    asm volatile("ldmatrix.sync.aligned.m8n8.x4.trans.shared.b16 {%0,%1,%2,%3}, [%4];"
                 : "=r"(r0), "=r"(r1), "=r"(r2), "=r"(r3) : "r"(addr));
}
__device__ __forceinline__ void cpa16(unsigned dst, const void* src) {
    asm volatile("cp.async.cg.shared.global [%0], [%1], 16;" :: "r"(dst), "l"(src));
}
__device__ __forceinline__ float ex2(float x) {
    float y; asm("ex2.approx.ftz.f32 %0, %1;" : "=f"(y) : "f"(x)); return y;
}

// ---------------------------------------------------------------------------
// Fused prologue: fp16 Q_aug (0.125*log2e folded), fp16 K_aug, fp16 V,
// pre-weighted bias (log2e*w_disc folded). Block = 64 t-rows of one head.
// Phase B vectorized: W read as float4, sQ/sK scalar broadcasts hoisted.
// ---------------------------------------------------------------------------
#define AP 68          // f32 pitch: 272B rows -> 16B-aligned float4 access
__global__ __launch_bounds__(256) void aug_kernel(
    const float* __restrict__ Q, const float* __restrict__ K,
    const float* __restrict__ V, const float* __restrict__ d_bias,
    const float* __restrict__ W,
    const float* __restrict__ w_std, const float* __restrict__ w_rec,
    const float* __restrict__ w_disc)
{
    __shared__ float sW[PD * PR];          // [j][16]
    __shared__ float sQ[64 * AP];
    __shared__ float sK[64 * AP];
    __shared__ float sLQ[64 * 16];
    __shared__ float sLK[64 * 16];

    const int tid = threadIdx.x;
    const int bh  = blockIdx.y;
    const int h   = bh % PH;
    const int t0  = blockIdx.x * 64;
    const size_t gbase = ((size_t)bh * PT + t0) * PD;

    // phase A: stage W, Q, K (float4)
    for (int i = tid; i < PD * PR / 4; i += 256)
        *reinterpret_cast<float4*>(&sW[i * 4]) =
            reinterpret_cast<const float4*>(W)[i];
#pragma unroll
    for (int k = 0; k < 4; k++) {
        const int i = tid + k * 256;             // float4 index
        const int r = i >> 4, c4 = (i & 15) * 4;
        *reinterpret_cast<float4*>(&sQ[r * AP + c4]) =
            reinterpret_cast<const float4*>(Q + gbase)[i];
        *reinterpret_cast<float4*>(&sK[r * AP + c4]) =
            reinterpret_cast<const float4*>(K + gbase)[i];
    }
    __syncthreads();

    // phase B: low-rank projections (4 threads/row, 4 rj each, W as float4)
    {
        const int r = tid >> 2, c4 = (tid & 3) * 4;
        float aq0 = 0.f, aq1 = 0.f, aq2 = 0.f, aq3 = 0.f;
        float ak0 = 0.f, ak1 = 0.f, ak2 = 0.f, ak3 = 0.f;
#pragma unroll
        for (int j = 0; j < PD; j++) {
            const float qv = sQ[r * AP + j];
            const float kv = sK[r * AP + j];
            const float4 wv = *reinterpret_cast<const float4*>(&sW[j * PR + c4]);
            aq0 = fmaf(qv, wv.x, aq0); aq1 = fmaf(qv, wv.y, aq1);
            aq2 = fmaf(qv, wv.z, aq2); aq3 = fmaf(qv, wv.w, aq3);
            ak0 = fmaf(kv, wv.x, ak0); ak1 = fmaf(kv, wv.y, ak1);
            ak2 = fmaf(kv, wv.z, ak2); ak3 = fmaf(kv, wv.w, ak3);
        }
        *reinterpret_cast<float4*>(&sLQ[r * 16 + c4]) = make_float4(aq0, aq1, aq2, aq3);
        *reinterpret_cast<float4*>(&sLK[r * 16 + c4]) = make_float4(ak0, ak1, ak2, ak3);
    }
    __syncthreads();

    // phase C: emit fp16 Q_aug / K_aug / V + bias (vectorized)
    {
        const float sstd = sqrtf(w_std[h]);
        const float srec = sqrtf(w_rec[h]);
        const float SCL = 0.125f * LOG2E;
        const int r = tid >> 2, d0 = (tid & 3) * 16;
        const size_t grow = gbase + (size_t)r * PD + d0;

        __half2 qo[8], ko[8], vo[8];
#pragma unroll
        for (int j = 0; j < 8; j++) {
            const int d = d0 + 2 * j;
            float q0, q1, k0, k1;
            if (d < PD_STD) {
                q0 = SCL * sstd * sQ[r * AP + d];   q1 = SCL * sstd * sQ[r * AP + d + 1];
                k0 = sstd * sK[r * AP + d];         k1 = sstd * sK[r * AP + d + 1];
            } else {
                const int rr = d - PD_STD;
                q0 = SCL * srec * sLK[r * 16 + rr]; q1 = SCL * srec * sLK[r * 16 + rr + 1];
                k0 = srec * sLQ[r * 16 + rr];       k1 = srec * sLQ[r * 16 + rr + 1];
            }
            qo[j] = __floats2half2_rn(q0, q1);
            ko[j] = __floats2half2_rn(k0, k1);
        }
#pragma unroll
        for (int j4 = 0; j4 < 4; j4++) {
            const float4 vv = *reinterpret_cast<const float4*>(&V[grow + 4 * j4]);
            vo[2 * j4]     = __floats2half2_rn(vv.x, vv.y);
            vo[2 * j4 + 1] = __floats2half2_rn(vv.z, vv.w);
        }
        *reinterpret_cast<uint4*>(&g_Qh[grow])     = *reinterpret_cast<uint4*>(&qo[0]);
        *reinterpret_cast<uint4*>(&g_Qh[grow + 8]) = *reinterpret_cast<uint4*>(&qo[4]);
        *reinterpret_cast<uint4*>(&g_Kh[grow])     = *reinterpret_cast<uint4*>(&ko[0]);
        *reinterpret_cast<uint4*>(&g_Kh[grow + 8]) = *reinterpret_cast<uint4*>(&ko[4]);
        *reinterpret_cast<uint4*>(&g_Vh[grow])     = *reinterpret_cast<uint4*>(&vo[0]);
        *reinterpret_cast<uint4*>(&g_Vh[grow + 8]) = *reinterpret_cast<uint4*>(&vo[4]);
        if (tid < 64)
            g_bw[(size_t)bh * PT + t0 + tid] =
                LOG2E * w_disc[h] * d_bias[(size_t)bh * PT + t0 + tid];
    }
}

// ---------------------------------------------------------------------------
// 128-key stage loader (SW128 xor swizzle) + f32 bias.
// ---------------------------------------------------------------------------
__device__ __forceinline__ void load_stage(unsigned sb, int stage,
                                           const __half* Kt, const __half* Vt,
                                           const float* bt, int tid)
{
    const unsigned kb = sb + (stage ? SK1 : SK0);
    const unsigned vb = sb + (stage ? SV1 : SV0);
    const unsigned bb = sb + (stage ? SB1 : SB0);
#pragma unroll
    for (int i = 0; i < 8; i++) {
        const int ch = tid + i * 128;
        const int r = ch >> 3, a = ch & 7;
        const unsigned off = (unsigned)(r * 128 + ((a ^ (r & 7)) << 4));
        cpa16(kb + off, Kt + r * 64 + a * 8);
        cpa16(vb + off, Vt + r * 64 + a * 8);
    }
    if (tid < 32) cpa16(bb + (unsigned)tid * 16u, bt + tid * 4);
    asm volatile("cp.async.commit_group;");
}

// ---------------------------------------------------------------------------
// Flash attention: HMMA.16816, 128-key tiles, f32 exp, row-sums via
// ones-column MMA. CTA = (head, 64-row q-tile), 128 threads, 3 CTA/SM.
// ---------------------------------------------------------------------------
__global__ __launch_bounds__(128, 3) void attn_kernel(float* __restrict__ out)
{
    extern __shared__ char sm[];
    const unsigned sb = (unsigned)__cvta_generic_to_shared(sm);

    const int bh = blockIdx.y;
    const int q_tile = (PT / QT - 1) - blockIdx.x;   // heavy tiles first
    const int nkt = q_tile / 2 + 1;                  // 128-key tiles
    const size_t base = (size_t)bh * PT * PD;
    const __half* Kg = g_Kh + base;
    const __half* Vg = g_Vh + base;
    const float*  bg = g_bw + (size_t)bh * PT;

    const int tid = threadIdx.x;
    const int w = tid >> 5, lane = tid & 31;
    const int g = lane >> 2, c = lane & 3;

    // ldmatrix address components
    const int kr  = 8 * (lane >> 4) + (lane & 7);                 // K rows (B frag)
    const int kao = (lane >> 3) & 1;
    const int qr  = 16 * w + 8 * ((lane >> 3) & 1) + (lane & 7);  // Q rows (A frag)
    const int qao = lane >> 4;
    const int vro = 8 * ((lane >> 3) & 1) + (lane & 7);           // V rows (trans B)
    const int vao = lane >> 4;
    const unsigned qrow_b = sb + SQ + (unsigned)qr * 128u;
    const int qsw = qr & 7, ksw = kr & 7, vsw = vro & 7;
    const int grow0 = q_tile * QT + 16 * w + g;      // this lane's first q row

    // stage0 K/V/bias + Q tile
    load_stage(sb, 0, Kg, Vg, bg, tid);
    {
        const __half* Qt = g_Qh + base + (size_t)q_tile * QT * PD;
#pragma unroll
        for (int i = 0; i < 4; i++) {
            const int ch = tid + i * 128;
            const int r = ch >> 3, a = ch & 7;
            cpa16(sb + SQ + (unsigned)(r * 128 + ((a ^ (r & 7)) << 4)), Qt + r * 64 + a * 8);
        }
        asm volatile("cp.async.commit_group;");
    }
    asm volatile("cp.async.wait_group 0;");
    __syncthreads();

    unsigned qf[4][4];
#pragma unroll
    for (int kk = 0; kk < 4; kk++)
        ldsm4(qf[kk][0], qf[kk][1], qf[kk][2], qf[kk][3],
              qrow_b + (unsigned)(((2 * kk + qao) ^ qsw) << 4));

    float acc[8][4];
#pragma unroll
    for (int nb = 0; nb < 8; nb++)
#pragma unroll
        for (int j = 0; j < 4; j++) acc[nb][j] = 0.f;
    float accl[4] = {0.f, 0.f, 0.f, 0.f};            // P row sums (ones-column mma)
    float m0 = -1e30f, m1 = -1e30f;

    int stage = 0;
    for (int kt = 0; kt < nkt; kt++) {
        if (kt) {
            asm volatile("cp.async.wait_group 0;");
            __syncthreads();
        }
        if (kt + 1 < nkt)
            load_stage(sb, stage ^ 1, Kg + (size_t)(kt + 1) * KT * PD,
                       Vg + (size_t)(kt + 1) * KT * PD, bg + (kt + 1) * KT, tid);

        const unsigned kb = sb + (stage ? SK1 : SK0);
        const unsigned vb = sb + (stage ? SV1 : SV0);
        const float* sB = (const float*)(sm + (stage ? SB1 : SB0));

        // ---- S (16x128 per warp): C-init = pre-weighted bias ----
        float s[16][4];
#pragma unroll
        for (int nb = 0; nb < 16; nb++) {
            const float2 bb = *reinterpret_cast<const float2*>(sB + 8 * nb + 2 * c);
            s[nb][0] = bb.x; s[nb][1] = bb.y;
            s[nb][2] = bb.x; s[nb][3] = bb.y;
        }
#pragma unroll
        for (int kk = 0; kk < 4; kk++) {
#pragma unroll
            for (int A2 = 0; A2 < 8; A2++) {
                unsigned b0, b1, b2, b3;
                ldsm4(b0, b1, b2, b3,
                      kb + (unsigned)((16 * A2 + kr) * 128 + (((2 * kk + kao) ^ ksw) << 4)));
                mma16816(s[2*A2][0], s[2*A2][1], s[2*A2][2], s[2*A2][3],
                         qf[kk][0], qf[kk][1], qf[kk][2], qf[kk][3], b0, b1);
                mma16816(s[2*A2+1][0], s[2*A2+1][1], s[2*A2+1][2], s[2*A2+1][3],
                         qf[kk][0], qf[kk][1], qf[kk][2], qf[kk][3], b2, b3);
            }
        }

        if (kt == nkt - 1) {   // causal mask, last 128-key tile
            const int kk0 = grow0 - kt * KT;        // local key bound, row g
#pragma unroll
            for (int nb = 0; nb < 16; nb++) {
                const int j0 = 8 * nb + 2 * c, j1 = j0 + 1;
                if (j0 > kk0)     s[nb][0] = -1e30f;
                if (j1 > kk0)     s[nb][1] = -1e30f;
                if (j0 > kk0 + 8) s[nb][2] = -1e30f;
                if (j1 > kk0 + 8) s[nb][3] = -1e30f;
            }
        }

        // ---- softmax over 128 keys (f32 base-2 exp) ----
        float rm0 = fmaxf(s[0][0], s[0][1]), rm1 = fmaxf(s[0][2], s[0][3]);
#pragma unroll
        for (int nb = 1; nb < 16; nb++) {
            rm0 = fmaxf(rm0, fmaxf(s[nb][0], s[nb][1]));
            rm1 = fmaxf(rm1, fmaxf(s[nb][2], s[nb][3]));
        }
        rm0 = fmaxf(rm0, __shfl_xor_sync(0xffffffffu, rm0, 1));
        rm0 = fmaxf(rm0, __shfl_xor_sync(0xffffffffu, rm0, 2));
        rm1 = fmaxf(rm1, __shfl_xor_sync(0xffffffffu, rm1, 1));
        rm1 = fmaxf(rm1, __shfl_xor_sync(0xffffffffu, rm1, 2));
        const float mn0 = fmaxf(m0, rm0), mn1 = fmaxf(m1, rm1);
        const float co0 = ex2(m0 - mn0), co1 = ex2(m1 - mn1);
        const bool moved = (mn0 > m0) | (mn1 > m1);
        m0 = mn0; m1 = mn1;

        unsigned pk0[16], pk1[16];   // P fragments (fp16), no f32 sum chain
#pragma unroll
        for (int nb = 0; nb < 16; nb++) {
            const float p00 = ex2(s[nb][0] - mn0);
            const float p01 = ex2(s[nb][1] - mn0);
            const float p10 = ex2(s[nb][2] - mn1);
            const float p11 = ex2(s[nb][3] - mn1);
            const __half2 h0 = __floats2half2_rn(p00, p01);
            const __half2 h1 = __floats2half2_rn(p10, p11);
            pk0[nb] = *reinterpret_cast<const unsigned*>(&h0);
            pk1[nb] = *reinterpret_cast<const unsigned*>(&h1);
        }

        if (__ballot_sync(0xffffffffu, moved)) {     // skip rescale when max stable
#pragma unroll
            for (int nb = 0; nb < 8; nb++) {
                acc[nb][0] *= co0; acc[nb][1] *= co0;
                acc[nb][2] *= co1; acc[nb][3] *= co1;
            }
            accl[0] *= co0; accl[1] *= co0;
            accl[2] *= co1; accl[3] *= co1;
        }

        // ---- O += P @ V; row sums via all-ones B fragment ----
        const unsigned ONES = 0x3C003C00u;
#pragma unroll
        for (int kk = 0; kk < 8; kk++) {
            const unsigned a0 = pk0[2 * kk],     a1 = pk1[2 * kk];
            const unsigned a2 = pk0[2 * kk + 1], a3 = pk1[2 * kk + 1];
#pragma unroll
            for (int A2 = 0; A2 < 4; A2++) {
                unsigned b0, b1, b2, b3;
                ldsm4t(b0, b1, b2, b3,
                       vb + (unsigned)((16 * kk + vro) * 128 + (((2 * A2 + vao) ^ vsw) << 4)));
                mma16816(acc[2*A2][0], acc[2*A2][1], acc[2*A2][2], acc[2*A2][3],
                         a0, a1, a2, a3, b0, b1);
                mma16816(acc[2*A2+1][0], acc[2*A2+1][1], acc[2*A2+1][2], acc[2*A2+1][3],
                         a0, a1, a2, a3, b2, b3);
            }
            mma16816(accl[0], accl[1], accl[2], accl[3], a0, a1, a2, a3, ONES, ONES);
        }
        stage ^= 1;
    }

    // ---- normalize + write (accl[0]=row g sum, accl[2]=row g+8 sum) ----
    const float inv0 = 1.0f / accl[0], inv1 = 1.0f / accl[2];
    float* og = out + base + ((size_t)q_tile * QT + 16 * w) * PD;
#pragma unroll
    for (int nb = 0; nb < 8; nb++) {
        *reinterpret_cast<float2*>(og + g * 64 + 8 * nb + 2 * c) =
            make_float2(acc[nb][0] * inv0, acc[nb][1] * inv0);
        *reinterpret_cast<float2*>(og + (g + 8) * 64 + 8 * nb + 2 * c) =
            make_float2(acc[nb][2] * inv1, acc[nb][3] * inv1);
    }
}

// ---------------------------------------------------------------------------
extern "C" void kernel_launch(void* const* d_in, const int* in_sizes, int n_in,
                              void* d_out, int out_size)
{
    const float* Q      = (const float*)d_in[0];
    const float* K      = (const float*)d_in[1];
    const float* V      = (const float*)d_in[2];
    const float* d_bias = (const float*)d_in[3];
    const float* W      = (const float*)d_in[4];
    const float* w_std  = (const float*)d_in[5];
    const float* w_rec  = (const float*)d_in[6];
    const float* w_disc = (const float*)d_in[7];
    float* out = (float*)d_out;

    cudaFuncSetAttribute(attn_kernel, cudaFuncAttributeMaxDynamicSharedMemorySize,
                         SMEM_BYTES);

    dim3 ag(PT / 64, PBH);
    aug_kernel<<<ag, 256>>>(Q, K, V, d_bias, W, w_std, w_rec, w_disc);

    dim3 grid(PT / QT, PBH);
    attn_kernel<<<grid, 128, SMEM_BYTES>>>(out);
}

// round 9
// speedup vs baseline: 6.9987x; 1.0252x over previous
#include <cuda_runtime.h>
#include <cuda_fp16.h>
#include <cstdint>

#define PB 2
#define PH 12
#define PT 2048
#define PD 64
#define PR 16
#define PD_STD 48
#define PBH (PB * PH)
#define QT 64
#define KT 128
#define LOG2E 1.4426950408889634f

// smem byte offsets (attn)
#define SQ  0          // Q tile 64x128B   = 8192
#define SK0 8192       // K tile 128x128B  = 16384
#define SK1 24576
#define SV0 40960      // V tile 128x128B  = 16384
#define SV1 57344
#define SB0 73728      // bias 128 f32 = 512
#define SB1 74240
#define SMEM_BYTES 74752

__device__ __half g_Qh[PBH * PT * PD];
__device__ __half g_Kh[PBH * PT * PD];
__device__ __half g_Vh[PBH * PT * PD];
__device__ float  g_bw[PBH * PT];

__device__ __forceinline__ void mma16816(float& d0, float& d1, float& d2, float& d3,
                                         unsigned a0, unsigned a1, unsigned a2, unsigned a3,
                                         unsigned b0, unsigned b1) {
    asm volatile(
        "mma.sync.aligned.m16n8k16.row.col.f32.f16.f16.f32 "
        "{%0,%1,%2,%3},{%4,%5,%6,%7},{%8,%9},{%0,%1,%2,%3};"
        : "+f"(d0), "+f"(d1), "+f"(d2), "+f"(d3)
        : "r"(a0), "r"(a1), "r"(a2), "r"(a3), "r"(b0), "r"(b1));
}
__device__ __forceinline__ void ldsm4(unsigned& r0, unsigned& r1, unsigned& r2, unsigned& r3,
                                      unsigned addr) {
    asm volatile("ldmatrix.sync.aligned.m8n8.x4.shared.b16 {%0,%1,%2,%3}, [%4];"
                 : "=r"(r0), "=r"(r1), "=r"(r2), "=r"(r3) : "r"(addr));
}
__device__ __forceinline__ void ldsm4t(unsigned& r0, unsigned& r1, unsigned& r2, unsigned& r3,
                                       unsigned addr) {
    asm volatile("ldmatrix.sync.aligned.m8n8.x4.trans.shared.b16 {%0,%1,%2,%3}, [%4];"
                 : "=r"(r0), "=r"(r1), "=r"(r2), "=r"(r3) : "r"(addr));
}
__device__ __forceinline__ void cpa16(unsigned dst, const void* src) {
    asm volatile("cp.async.cg.shared.global [%0], [%1], 16;" :: "r"(dst), "l"(src));
}
__device__ __forceinline__ float ex2(float x) {
    float y; asm("ex2.approx.ftz.f32 %0, %1;" : "=f"(y) : "f"(x)); return y;
}
// packed fp16 exp2: f32 subtract (precision), half2 pack, MUFU f16x2
__device__ __forceinline__ unsigned ex2_pk(float x0, float x1) {
    const __half2 h = __floats2half2_rn(x0, x1);
    unsigned y;
    asm("ex2.approx.f16x2 %0, %1;" : "=r"(y) : "r"(*reinterpret_cast<const unsigned*>(&h)));
    return y;
}

// ---------------------------------------------------------------------------
// Fused prologue: fp16 Q_aug (0.125*log2e folded), fp16 K_aug, fp16 V,
// pre-weighted bias (log2e*w_disc folded). Block = 64 t-rows of one head.
// ---------------------------------------------------------------------------
#define AP 68          // f32 pitch: 272B rows -> 16B-aligned float4 access
__global__ __launch_bounds__(256) void aug_kernel(
    const float* __restrict__ Q, const float* __restrict__ K,
    const float* __restrict__ V, const float* __restrict__ d_bias,
    const float* __restrict__ W,
    const float* __restrict__ w_std, const float* __restrict__ w_rec,
    const float* __restrict__ w_disc)
{
    __shared__ float sW[PD * PR];          // [j][16]
    __shared__ float sQ[64 * AP];
    __shared__ float sK[64 * AP];
    __shared__ float sLQ[64 * 16];
    __shared__ float sLK[64 * 16];

    const int tid = threadIdx.x;
    const int bh  = blockIdx.y;
    const int h   = bh % PH;
    const int t0  = blockIdx.x * 64;
    const size_t gbase = ((size_t)bh * PT + t0) * PD;

    // phase A: stage W, Q, K (float4)
    for (int i = tid; i < PD * PR / 4; i += 256)
        *reinterpret_cast<float4*>(&sW[i * 4]) =
            reinterpret_cast<const float4*>(W)[i];
#pragma unroll
    for (int k = 0; k < 4; k++) {
        const int i = tid + k * 256;             // float4 index
        const int r = i >> 4, c4 = (i & 15) * 4;
        *reinterpret_cast<float4*>(&sQ[r * AP + c4]) =
            reinterpret_cast<const float4*>(Q + gbase)[i];
        *reinterpret_cast<float4*>(&sK[r * AP + c4]) =
            reinterpret_cast<const float4*>(K + gbase)[i];
    }
    __syncthreads();

    // phase B: low-rank projections (4 threads/row, 4 rj each, W as float4)
    {
        const int r = tid >> 2, c4 = (tid & 3) * 4;
        float aq0 = 0.f, aq1 = 0.f, aq2 = 0.f, aq3 = 0.f;
        float ak0 = 0.f, ak1 = 0.f, ak2 = 0.f, ak3 = 0.f;
#pragma unroll
        for (int j = 0; j < PD; j++) {
            const float qv = sQ[r * AP + j];
            const float kv = sK[r * AP + j];
            const float4 wv = *reinterpret_cast<const float4*>(&sW[j * PR + c4]);
            aq0 = fmaf(qv, wv.x, aq0); aq1 = fmaf(qv, wv.y, aq1);
            aq2 = fmaf(qv, wv.z, aq2); aq3 = fmaf(qv, wv.w, aq3);
            ak0 = fmaf(kv, wv.x, ak0); ak1 = fmaf(kv, wv.y, ak1);
            ak2 = fmaf(kv, wv.z, ak2); ak3 = fmaf(kv, wv.w, ak3);
        }
        *reinterpret_cast<float4*>(&sLQ[r * 16 + c4]) = make_float4(aq0, aq1, aq2, aq3);
        *reinterpret_cast<float4*>(&sLK[r * 16 + c4]) = make_float4(ak0, ak1, ak2, ak3);
    }
    __syncthreads();

    // phase C: emit fp16 Q_aug / K_aug / V + bias (vectorized)
    {
        const float sstd = sqrtf(w_std[h]);
        const float srec = sqrtf(w_rec[h]);
        const float SCL = 0.125f * LOG2E;
        const int r = tid >> 2, d0 = (tid & 3) * 16;
        const size_t grow = gbase + (size_t)r * PD + d0;

        __half2 qo[8], ko[8], vo[8];
#pragma unroll
        for (int j = 0; j < 8; j++) {
            const int d = d0 + 2 * j;
            float q0, q1, k0, k1;
            if (d < PD_STD) {
                q0 = SCL * sstd * sQ[r * AP + d];   q1 = SCL * sstd * sQ[r * AP + d + 1];
                k0 = sstd * sK[r * AP + d];         k1 = sstd * sK[r * AP + d + 1];
            } else {
                const int rr = d - PD_STD;
                q0 = SCL * srec * sLK[r * 16 + rr]; q1 = SCL * srec * sLK[r * 16 + rr + 1];
                k0 = srec * sLQ[r * 16 + rr];       k1 = srec * sLQ[r * 16 + rr + 1];
            }
            qo[j] = __floats2half2_rn(q0, q1);
            ko[j] = __floats2half2_rn(k0, k1);
        }
#pragma unroll
        for (int j4 = 0; j4 < 4; j4++) {
            const float4 vv = *reinterpret_cast<const float4*>(&V[grow + 4 * j4]);
            vo[2 * j4]     = __floats2half2_rn(vv.x, vv.y);
            vo[2 * j4 + 1] = __floats2half2_rn(vv.z, vv.w);
        }
        *reinterpret_cast<uint4*>(&g_Qh[grow])     = *reinterpret_cast<uint4*>(&qo[0]);
        *reinterpret_cast<uint4*>(&g_Qh[grow + 8]) = *reinterpret_cast<uint4*>(&qo[4]);
        *reinterpret_cast<uint4*>(&g_Kh[grow])     = *reinterpret_cast<uint4*>(&ko[0]);
        *reinterpret_cast<uint4*>(&g_Kh[grow + 8]) = *reinterpret_cast<uint4*>(&ko[4]);
        *reinterpret_cast<uint4*>(&g_Vh[grow])     = *reinterpret_cast<uint4*>(&vo[0]);
        *reinterpret_cast<uint4*>(&g_Vh[grow + 8]) = *reinterpret_cast<uint4*>(&vo[4]);
        if (tid < 64)
            g_bw[(size_t)bh * PT + t0 + tid] =
                LOG2E * w_disc[h] * d_bias[(size_t)bh * PT + t0 + tid];
    }
}

// ---------------------------------------------------------------------------
// 128-key stage loader (SW128 xor swizzle) + f32 bias.
// ---------------------------------------------------------------------------
__device__ __forceinline__ void load_stage(unsigned sb, int stage,
                                           const __half* Kt, const __half* Vt,
                                           const float* bt, int tid)
{
    const unsigned kb = sb + (stage ? SK1 : SK0);
    const unsigned vb = sb + (stage ? SV1 : SV0);
    const unsigned bb = sb + (stage ? SB1 : SB0);
#pragma unroll
    for (int i = 0; i < 8; i++) {
        const int ch = tid + i * 128;
        const int r = ch >> 3, a = ch & 7;
        const unsigned off = (unsigned)(r * 128 + ((a ^ (r & 7)) << 4));
        cpa16(kb + off, Kt + r * 64 + a * 8);
        cpa16(vb + off, Vt + r * 64 + a * 8);
    }
    if (tid < 32) cpa16(bb + (unsigned)tid * 16u, bt + tid * 4);
    asm volatile("cp.async.commit_group;");
}

// ---------------------------------------------------------------------------
// Flash attention: HMMA.16816, 128-key tiles, fp16-packed exp interleaved
// into the PV mma loop, row-sums via ones-column MMA.
// CTA = (head, 64-row q-tile), 128 threads, 3 CTA/SM.
// ---------------------------------------------------------------------------
__global__ __launch_bounds__(128, 3) void attn_kernel(float* __restrict__ out)
{
    extern __shared__ char sm[];
    const unsigned sb = (unsigned)__cvta_generic_to_shared(sm);

    const int bh = blockIdx.y;
    const int q_tile = (PT / QT - 1) - blockIdx.x;   // heavy tiles first
    const int nkt = q_tile / 2 + 1;                  // 128-key tiles
    const size_t base = (size_t)bh * PT * PD;
    const __half* Kg = g_Kh + base;
    const __half* Vg = g_Vh + base;
    const float*  bg = g_bw + (size_t)bh * PT;

    const int tid = threadIdx.x;
    const int w = tid >> 5, lane = tid & 31;
    const int g = lane >> 2, c = lane & 3;

    // ldmatrix address components
    const int kr  = 8 * (lane >> 4) + (lane & 7);                 // K rows (B frag)
    const int kao = (lane >> 3) & 1;
    const int qr  = 16 * w + 8 * ((lane >> 3) & 1) + (lane & 7);  // Q rows (A frag)
    const int qao = lane >> 4;
    const int vro = 8 * ((lane >> 3) & 1) + (lane & 7);           // V rows (trans B)
    const int vao = lane >> 4;
    const unsigned qrow_b = sb + SQ + (unsigned)qr * 128u;
    const int qsw = qr & 7, ksw = kr & 7, vsw = vro & 7;
    const int grow0 = q_tile * QT + 16 * w + g;      // this lane's first q row

    // stage0 K/V/bias + Q tile
    load_stage(sb, 0, Kg, Vg, bg, tid);
    {
        const __half* Qt = g_Qh + base + (size_t)q_tile * QT * PD;
#pragma unroll
        for (int i = 0; i < 4; i++) {
            const int ch = tid + i * 128;
            const int r = ch >> 3, a = ch & 7;
            cpa16(sb + SQ + (unsigned)(r * 128 + ((a ^ (r & 7)) << 4)), Qt + r * 64 + a * 8);
        }
        asm volatile("cp.async.commit_group;");
    }
    asm volatile("cp.async.wait_group 0;");
    __syncthreads();

    unsigned qf[4][4];
#pragma unroll
    for (int kk = 0; kk < 4; kk++)
        ldsm4(qf[kk][0], qf[kk][1], qf[kk][2], qf[kk][3],
              qrow_b + (unsigned)(((2 * kk + qao) ^ qsw) << 4));

    float acc[8][4];
#pragma unroll
    for (int nb = 0; nb < 8; nb++)
#pragma unroll
        for (int j = 0; j < 4; j++) acc[nb][j] = 0.f;
    float accl[4] = {0.f, 0.f, 0.f, 0.f};            // P row sums (ones-column mma)
    float m0 = -1e30f, m1 = -1e30f;

    int stage = 0;
    for (int kt = 0; kt < nkt; kt++) {
        if (kt) {
            asm volatile("cp.async.wait_group 0;");
            __syncthreads();
        }
        if (kt + 1 < nkt)
            load_stage(sb, stage ^ 1, Kg + (size_t)(kt + 1) * KT * PD,
                       Vg + (size_t)(kt + 1) * KT * PD, bg + (kt + 1) * KT, tid);

        const unsigned kb = sb + (stage ? SK1 : SK0);
        const unsigned vb = sb + (stage ? SV1 : SV0);
        const float* sB = (const float*)(sm + (stage ? SB1 : SB0));

        // ---- S (16x128 per warp): C-init = pre-weighted bias ----
        float s[16][4];
#pragma unroll
        for (int nb = 0; nb < 16; nb++) {
            const float2 bb = *reinterpret_cast<const float2*>(sB + 8 * nb + 2 * c);
            s[nb][0] = bb.x; s[nb][1] = bb.y;
            s[nb][2] = bb.x; s[nb][3] = bb.y;
        }
#pragma unroll
        for (int kk = 0; kk < 4; kk++) {
#pragma unroll
            for (int A2 = 0; A2 < 8; A2++) {
                unsigned b0, b1, b2, b3;
                ldsm4(b0, b1, b2, b3,
                      kb + (unsigned)((16 * A2 + kr) * 128 + (((2 * kk + kao) ^ ksw) << 4)));
                mma16816(s[2*A2][0], s[2*A2][1], s[2*A2][2], s[2*A2][3],
                         qf[kk][0], qf[kk][1], qf[kk][2], qf[kk][3], b0, b1);
                mma16816(s[2*A2+1][0], s[2*A2+1][1], s[2*A2+1][2], s[2*A2+1][3],
                         qf[kk][0], qf[kk][1], qf[kk][2], qf[kk][3], b2, b3);
            }
        }

        if (kt == nkt - 1) {   // causal mask, last 128-key tile
            const int kk0 = grow0 - kt * KT;        // local key bound, row g
#pragma unroll
            for (int nb = 0; nb < 16; nb++) {
                const int j0 = 8 * nb + 2 * c, j1 = j0 + 1;
                if (j0 > kk0)     s[nb][0] = -1e30f;
                if (j1 > kk0)     s[nb][1] = -1e30f;
                if (j0 > kk0 + 8) s[nb][2] = -1e30f;
                if (j1 > kk0 + 8) s[nb][3] = -1e30f;
            }
        }

        // ---- row max over 128 keys (f32) ----
        float rm0 = fmaxf(s[0][0], s[0][1]), rm1 = fmaxf(s[0][2], s[0][3]);
#pragma unroll
        for (int nb = 1; nb < 16; nb++) {
            rm0 = fmaxf(rm0, fmaxf(s[nb][0], s[nb][1]));
            rm1 = fmaxf(rm1, fmaxf(s[nb][2], s[nb][3]));
        }
        rm0 = fmaxf(rm0, __shfl_xor_sync(0xffffffffu, rm0, 1));
        rm0 = fmaxf(rm0, __shfl_xor_sync(0xffffffffu, rm0, 2));
        rm1 = fmaxf(rm1, __shfl_xor_sync(0xffffffffu, rm1, 1));
        rm1 = fmaxf(rm1, __shfl_xor_sync(0xffffffffu, rm1, 2));
        const float mn0 = fmaxf(m0, rm0), mn1 = fmaxf(m1, rm1);
        const float co0 = ex2(m0 - mn0), co1 = ex2(m1 - mn1);
        const bool moved = (mn0 > m0) | (mn1 > m1);
        m0 = mn0; m1 = mn1;

        if (__ballot_sync(0xffffffffu, moved)) {     // skip rescale when max stable
#pragma unroll
            for (int nb = 0; nb < 8; nb++) {
                acc[nb][0] *= co0; acc[nb][1] *= co0;
                acc[nb][2] *= co1; acc[nb][3] *= co1;
            }
            accl[0] *= co0; accl[1] *= co0;
            accl[2] *= co1; accl[3] *= co1;
        }

        // ---- fused exp + PV: per kk, make P fragments then mma them ----
        const unsigned ONES = 0x3C003C00u;
#pragma unroll
        for (int kk = 0; kk < 8; kk++) {
            // packed fp16 exp for this kk's two S row-blocks (MUFU overlaps
            // with the previous kk's tensor work)
            const unsigned a0 = ex2_pk(s[2*kk][0]   - mn0, s[2*kk][1]   - mn0);
            const unsigned a1 = ex2_pk(s[2*kk][2]   - mn1, s[2*kk][3]   - mn1);
            const unsigned a2 = ex2_pk(s[2*kk+1][0] - mn0, s[2*kk+1][1] - mn0);
            const unsigned a3 = ex2_pk(s[2*kk+1][2] - mn1, s[2*kk+1][3] - mn1);
#pragma unroll
            for (int A2 = 0; A2 < 4; A2++) {
                unsigned b0, b1, b2, b3;
                ldsm4t(b0, b1, b2, b3,
                       vb + (unsigned)((16 * kk + vro) * 128 + (((2 * A2 + vao) ^ vsw) << 4)));
                mma16816(acc[2*A2][0], acc[2*A2][1], acc[2*A2][2], acc[2*A2][3],
                         a0, a1, a2, a3, b0, b1);
                mma16816(acc[2*A2+1][0], acc[2*A2+1][1], acc[2*A2+1][2], acc[2*A2+1][3],
                         a0, a1, a2, a3, b2, b3);
            }
            mma16816(accl[0], accl[1], accl[2], accl[3], a0, a1, a2, a3, ONES, ONES);
        }
        stage ^= 1;
    }

    // ---- normalize + write (accl[0]=row g sum, accl[2]=row g+8 sum) ----
    const float inv0 = 1.0f / accl[0], inv1 = 1.0f / accl[2];
    float* og = out + base + ((size_t)q_tile * QT + 16 * w) * PD;
#pragma unroll
    for (int nb = 0; nb < 8; nb++) {
        *reinterpret_cast<float2*>(og + g * 64 + 8 * nb + 2 * c) =
            make_float2(acc[nb][0] * inv0, acc[nb][1] * inv0);
        *reinterpret_cast<float2*>(og + (g + 8) * 64 + 8 * nb + 2 * c) =
            make_float2(acc[nb][2] * inv1, acc[nb][3] * inv1);
    }
}

// ---------------------------------------------------------------------------
extern "C" void kernel_launch(void* const* d_in, const int* in_sizes, int n_in,
                              void* d_out, int out_size)
{
    const float* Q      = (const float*)d_in[0];
    const float* K      = (const float*)d_in[1];
    const float* V      = (const float*)d_in[2];
    const float* d_bias = (const float*)d_in[3];
    const float* W      = (const float*)d_in[4];
    const float* w_std  = (const float*)d_in[5];
    const float* w_rec  = (const float*)d_in[6];
    const float* w_disc = (const float*)d_in[7];
    float* out = (float*)d_out;

    cudaFuncSetAttribute(attn_kernel, cudaFuncAttributeMaxDynamicSharedMemorySize,
                         SMEM_BYTES);

    dim3 ag(PT / 64, PBH);
    aug_kernel<<<ag, 256>>>(Q, K, V, d_bias, W, w_std, w_rec, w_disc);

    dim3 grid(PT / QT, PBH);
    attn_kernel<<<grid, 128, SMEM_BYTES>>>(out);
}